// round 10
// baseline (speedup 1.0000x reference)
#include <cuda_runtime.h>
#include <cuda_fp16.h>
#include <math.h>
#include <stdint.h>

#define D_MODEL 1024
#define NUM_HEADS 16
#define D_HEAD 64
#define BATCH 2
#define SEQ 2048
#define BHN (BATCH*NUM_HEADS)

// -------- scratch (static device memory; no runtime allocation) --------
__device__ float  g_q  [(size_t)BATCH*SEQ*D_MODEL];          // 16 MB fp32
__device__ __half g_k  [(size_t)BATCH*SEQ*D_MODEL];          // 8 MB fp16
__device__ __half g_vT [(size_t)BHN*D_HEAD*SEQ];             // 8 MB fp16, [bh][d][s]
__device__ __half g_qer[(size_t)BHN*SEQ*SEQ];                // 256 MB fp16
__device__ __half g_xh [(size_t)BATCH*SEQ*D_MODEL];          // 8 MB fp16 (x pre-converted)
__device__ __half g_wh [3][(size_t)D_MODEL*D_MODEL];         // 6 MB fp16 (Wq,Wk,Wv)

// ---------------- helpers ----------------
__device__ __forceinline__ void mma_f16(float& c0, float& c1, float& c2, float& c3,
                                        uint32_t a0, uint32_t a1, uint32_t a2, uint32_t a3,
                                        uint32_t b0, uint32_t b1) {
    asm volatile(
        "mma.sync.aligned.m16n8k16.row.col.f32.f16.f16.f32 "
        "{%0,%1,%2,%3}, {%4,%5,%6,%7}, {%8,%9}, {%0,%1,%2,%3};"
        : "+f"(c0), "+f"(c1), "+f"(c2), "+f"(c3)
        : "r"(a0), "r"(a1), "r"(a2), "r"(a3), "r"(b0), "r"(b1));
}
__device__ __forceinline__ void ldsm_x4(uint32_t& r0, uint32_t& r1, uint32_t& r2, uint32_t& r3,
                                        uint32_t saddr) {
    asm volatile("ldmatrix.sync.aligned.m8n8.x4.shared.b16 {%0,%1,%2,%3}, [%4];"
                 : "=r"(r0), "=r"(r1), "=r"(r2), "=r"(r3) : "r"(saddr));
}
__device__ __forceinline__ uint32_t pack_h2(float x, float y) {
    __half2 h = __floats2half2_rn(x, y);
    return *(uint32_t*)&h;
}
__device__ __forceinline__ void cp_async16(uint32_t saddr, const void* g) {
    asm volatile("cp.async.cg.shared.global [%0], [%1], 16;" :: "r"(saddr), "l"(g));
}
#define CP_COMMIT() asm volatile("cp.async.commit_group;")
#define CP_WAIT0()  asm volatile("cp.async.wait_group 0;")

// smem geometry for fp16 tensor-core GEMMs: [2 buf][128 rows][HP] halves
#define HP 40
#define GEMM_SMEM_BYTES (2*128*HP*2*2)   // A + B -> 40960 B

// ============================================================
// Kernel 0: convert x, Wq, Wk, Wv to fp16 once.
// ============================================================
__global__ __launch_bounds__(256)
void cvt_inputs_kernel(const float* __restrict__ x,
                       const float* __restrict__ Wq,
                       const float* __restrict__ Wk,
                       const float* __restrict__ Wv)
{
    const size_t XN = (size_t)BATCH*SEQ*D_MODEL;
    const size_t WN = (size_t)D_MODEL*D_MODEL;
    size_t i = ((size_t)blockIdx.x * blockDim.x + threadIdx.x) * 4;
    const float* src; __half* dst; size_t off;
    if (i < XN)              { src = x;  dst = g_xh;    off = i; }
    else if (i < XN + WN)    { src = Wq; dst = g_wh[0]; off = i - XN; }
    else if (i < XN + 2*WN)  { src = Wk; dst = g_wh[1]; off = i - XN - WN; }
    else if (i < XN + 3*WN)  { src = Wv; dst = g_wh[2]; off = i - XN - 2*WN; }
    else return;
    float4 v = *(const float4*)(src + off);
    *(uint32_t*)(dst + off)     = pack_h2(v.x, v.y);
    *(uint32_t*)(dst + off + 2) = pack_h2(v.z, v.w);
}

// ============================================================
// Kernel 1 (fp16 tensor core): Q/K/V projection, cp.async loaders.
// ============================================================
__global__ __launch_bounds__(256, 2)
void qkv_tc_kernel(const float* __restrict__ bq,
                   const float* __restrict__ bk,
                   const float* __restrict__ bv)
{
    const __half* Wh = g_wh[blockIdx.z];
    const float* bias = (blockIdx.z == 0) ? bq : (blockIdx.z == 1) ? bk : bv;

    extern __shared__ __half smh[];
    __half* As = smh;                // [2][128][HP]
    __half* Bs = smh + 2*128*HP;     // [2][128][HP]
    const uint32_t As_u = (uint32_t)__cvta_generic_to_shared(As);
    const uint32_t Bs_u = (uint32_t)__cvta_generic_to_shared(Bs);

    const int m0 = blockIdx.y * 128;
    const int n0 = blockIdx.x * 128;
    const int tid = threadIdx.x;
    const int wid = tid >> 5;
    const int lane = tid & 31;
    const int gid = lane >> 2;
    const int tig = lane & 3;
    const int wm = wid >> 2;
    const int wn = wid & 3;

    const int lmA_row = (lane & 7) + ((lane >> 3) & 1) * 8;
    const int lmA_kof = ((lane >> 4) & 1) * 8;
    const int lmB_row = (lane & 7) + ((lane >> 4) & 1) * 8;
    const int lmB_kof = ((lane >> 3) & 1) * 8;

    const __half* Ag = g_xh + (size_t)m0 * D_MODEL;
    const __half* Bg = Wh + (size_t)n0 * D_MODEL;

    // loader geometry: threads 0..127 -> A rows, 128..255 -> B rows; 4 x 16B per row
    const int larr = tid >> 7;
    const int lrow = tid & 127;
    const __half* lsrc = (larr ? Bg : Ag) + (size_t)lrow * D_MODEL;
    const uint32_t ldst = (larr ? Bs_u : As_u) + 2u * (uint32_t)(lrow * HP);

    float c[4][4][4];
#pragma unroll
    for (int mt = 0; mt < 4; mt++)
#pragma unroll
        for (int nt = 0; nt < 4; nt++)
#pragma unroll
            for (int r = 0; r < 4; r++) c[mt][nt][r] = 0.f;

    // prologue: chunk 0 -> buffer 0
#pragma unroll
    for (int j = 0; j < 4; j++)
        cp_async16(ldst + j*16, lsrc + j*8);
    CP_COMMIT();

    for (int k0 = 0; k0 < D_MODEL; k0 += 32) {
        const int buf = (k0 >> 5) & 1;
        CP_WAIT0();
        __syncthreads();
        if (k0 + 32 < D_MODEL) {
            const uint32_t boff = (uint32_t)((buf ^ 1) * 128 * HP * 2);
#pragma unroll
            for (int j = 0; j < 4; j++)
                cp_async16(ldst + boff + j*16, lsrc + k0 + 32 + j*8);
        }
        CP_COMMIT();

#pragma unroll
        for (int ks = 0; ks < 2; ks++) {
            const int kk = ks * 16;
            uint32_t a[4][4];
#pragma unroll
            for (int mt = 0; mt < 4; mt++) {
                const uint32_t addr = As_u +
                    2u * (uint32_t)((buf*128 + wm*64 + mt*16 + lmA_row) * HP + kk + lmA_kof);
                ldsm_x4(a[mt][0], a[mt][1], a[mt][2], a[mt][3], addr);
            }
#pragma unroll
            for (int ntp = 0; ntp < 2; ntp++) {
                uint32_t b00, b01, b10, b11;
                const uint32_t addr = Bs_u +
                    2u * (uint32_t)((buf*128 + wn*32 + ntp*16 + lmB_row) * HP + kk + lmB_kof);
                ldsm_x4(b00, b01, b10, b11, addr);
#pragma unroll
                for (int mt = 0; mt < 4; mt++) {
                    mma_f16(c[mt][2*ntp][0], c[mt][2*ntp][1], c[mt][2*ntp][2], c[mt][2*ntp][3],
                            a[mt][0], a[mt][1], a[mt][2], a[mt][3], b00, b01);
                    mma_f16(c[mt][2*ntp+1][0], c[mt][2*ntp+1][1], c[mt][2*ntp+1][2], c[mt][2*ntp+1][3],
                            a[mt][0], a[mt][1], a[mt][2], a[mt][3], b10, b11);
                }
            }
        }
    }

    if (blockIdx.z == 0) {
#pragma unroll
        for (int nt = 0; nt < 4; nt++) {
            const int col = n0 + wn*32 + nt*8 + 2*tig;
            const float2 bb = *(const float2*)(bias + col);
#pragma unroll
            for (int mt = 0; mt < 4; mt++) {
                const int row = m0 + wm*64 + mt*16 + gid;
                *(float2*)(g_q + (size_t)row * D_MODEL + col) =
                    make_float2(c[mt][nt][0] + bb.x, c[mt][nt][1] + bb.y);
                *(float2*)(g_q + (size_t)(row + 8) * D_MODEL + col) =
                    make_float2(c[mt][nt][2] + bb.x, c[mt][nt][3] + bb.y);
            }
        }
    } else if (blockIdx.z == 1) {
#pragma unroll
        for (int nt = 0; nt < 4; nt++) {
            const int col = n0 + wn*32 + nt*8 + 2*tig;
            const float2 bb = *(const float2*)(bias + col);
#pragma unroll
            for (int mt = 0; mt < 4; mt++) {
                const int row = m0 + wm*64 + mt*16 + gid;
                *(__half2*)(g_k + (size_t)row * D_MODEL + col) =
                    __floats2half2_rn(c[mt][nt][0] + bb.x, c[mt][nt][1] + bb.y);
                *(__half2*)(g_k + (size_t)(row + 8) * D_MODEL + col) =
                    __floats2half2_rn(c[mt][nt][2] + bb.x, c[mt][nt][3] + bb.y);
            }
        }
    } else {
#pragma unroll
        for (int nt = 0; nt < 4; nt++) {
            const int col = n0 + wn*32 + nt*8 + 2*tig;
            const float2 bb = *(const float2*)(bias + col);
            const int hh = col >> 6;
            const int d0 = col & 63;
#pragma unroll
            for (int mt = 0; mt < 4; mt++) {
                const int row = m0 + wm*64 + mt*16 + gid;
                const int bidx = row >> 11;
                const int sidx = row & 2047;
                __half* base = g_vT + ((size_t)(bidx*NUM_HEADS + hh) * D_HEAD + d0) * SEQ;
                base[sidx]            = __float2half(c[mt][nt][0] + bb.x);
                base[SEQ + sidx]      = __float2half(c[mt][nt][1] + bb.y);
                base[sidx + 8]        = __float2half(c[mt][nt][2] + bb.x);
                base[SEQ + sidx + 8]  = __float2half(c[mt][nt][3] + bb.y);
            }
        }
    }
}

// ============================================================
// Kernel 2 (fp16 tensor core): QEr[bh][s][j] = q_head[s,:] . Er[j,:]
// ============================================================
__global__ __launch_bounds__(256, 2)
void qer_tc_kernel(const float* __restrict__ Er)
{
    const int bh = blockIdx.z;
    const int b = bh >> 4, h = bh & 15;
    const int j0 = blockIdx.x * 128;
    const int s0 = blockIdx.y * 128;
    if (s0 + j0 + 254 < SEQ - 1) return;

    extern __shared__ __half smh[];
    __half* As = smh;
    __half* Bs = smh + 2*128*HP;
    const uint32_t As_u = (uint32_t)__cvta_generic_to_shared(As);
    const uint32_t Bs_u = (uint32_t)__cvta_generic_to_shared(Bs);

    const int tid = threadIdx.x;
    const int wid = tid >> 5;
    const int lane = tid & 31;
    const int gid = lane >> 2;
    const int tig = lane & 3;
    const int wm = wid >> 2;
    const int wn = wid & 3;

    const int lmA_row = (lane & 7) + ((lane >> 3) & 1) * 8;
    const int lmA_kof = ((lane >> 4) & 1) * 8;
    const int lmB_row = (lane & 7) + ((lane >> 4) & 1) * 8;
    const int lmB_kof = ((lane >> 3) & 1) * 8;

    const float* Ag = g_q + ((size_t)b * SEQ + s0) * D_MODEL + (size_t)h * D_HEAD;
    const float* Bg = Er + (size_t)j0 * D_HEAD;

    float c[4][4][4];
#pragma unroll
    for (int mt = 0; mt < 4; mt++)
#pragma unroll
        for (int nt = 0; nt < 4; nt++)
#pragma unroll
            for (int r = 0; r < 4; r++) c[mt][nt][r] = 0.f;

    const int lrow = tid >> 3;
    const int lc4  = (tid & 7) * 4;

    float4 pa[4], pb[4];
#pragma unroll
    for (int i = 0; i < 4; i++) {
        pa[i] = *(const float4*)(Ag + (size_t)(lrow + i*32) * D_MODEL + lc4);
        pb[i] = *(const float4*)(Bg + (size_t)(lrow + i*32) * D_HEAD + lc4);
    }
#pragma unroll
    for (int i = 0; i < 4; i++) {
        __half* da = As + (lrow + i*32) * HP + lc4;
        *(uint32_t*)da       = pack_h2(pa[i].x, pa[i].y);
        *(uint32_t*)(da + 2) = pack_h2(pa[i].z, pa[i].w);
        __half* db = Bs + (lrow + i*32) * HP + lc4;
        *(uint32_t*)db       = pack_h2(pb[i].x, pb[i].y);
        *(uint32_t*)(db + 2) = pack_h2(pb[i].z, pb[i].w);
    }
    __syncthreads();

    for (int k0 = 0; k0 < D_HEAD; k0 += 32) {
        const int buf = (k0 >> 5) & 1;
        const bool has_next = (k0 + 32) < D_HEAD;
        if (has_next) {
#pragma unroll
            for (int i = 0; i < 4; i++) {
                pa[i] = *(const float4*)(Ag + (size_t)(lrow + i*32) * D_MODEL + k0 + 32 + lc4);
                pb[i] = *(const float4*)(Bg + (size_t)(lrow + i*32) * D_HEAD + k0 + 32 + lc4);
            }
        }
#pragma unroll
        for (int ks = 0; ks < 2; ks++) {
            const int kk = ks * 16;
            uint32_t a[4][4];
#pragma unroll
            for (int mt = 0; mt < 4; mt++) {
                const uint32_t addr = As_u +
                    2u * (uint32_t)((buf*128 + wm*64 + mt*16 + lmA_row) * HP + kk + lmA_kof);
                ldsm_x4(a[mt][0], a[mt][1], a[mt][2], a[mt][3], addr);
            }
#pragma unroll
            for (int ntp = 0; ntp < 2; ntp++) {
                uint32_t b00, b01, b10, b11;
                const uint32_t addr = Bs_u +
                    2u * (uint32_t)((buf*128 + wn*32 + ntp*16 + lmB_row) * HP + kk + lmB_kof);
                ldsm_x4(b00, b01, b10, b11, addr);
#pragma unroll
                for (int mt = 0; mt < 4; mt++) {
                    mma_f16(c[mt][2*ntp][0], c[mt][2*ntp][1], c[mt][2*ntp][2], c[mt][2*ntp][3],
                            a[mt][0], a[mt][1], a[mt][2], a[mt][3], b00, b01);
                    mma_f16(c[mt][2*ntp+1][0], c[mt][2*ntp+1][1], c[mt][2*ntp+1][2], c[mt][2*ntp+1][3],
                            a[mt][0], a[mt][1], a[mt][2], a[mt][3], b10, b11);
                }
            }
        }
        if (has_next) {
            const int nb = buf ^ 1;
#pragma unroll
            for (int i = 0; i < 4; i++) {
                __half* da = As + nb*128*HP + (lrow + i*32) * HP + lc4;
                *(uint32_t*)da       = pack_h2(pa[i].x, pa[i].y);
                *(uint32_t*)(da + 2) = pack_h2(pa[i].z, pa[i].w);
                __half* db = Bs + nb*128*HP + (lrow + i*32) * HP + lc4;
                *(uint32_t*)db       = pack_h2(pb[i].x, pb[i].y);
                *(uint32_t*)(db + 2) = pack_h2(pb[i].z, pb[i].w);
            }
            __syncthreads();
        }
    }

    __half* dst = g_qer + (size_t)bh * SEQ * SEQ;
#pragma unroll
    for (int nt = 0; nt < 4; nt++) {
        const int col = j0 + wn*32 + nt*8 + 2*tig;
#pragma unroll
        for (int mt = 0; mt < 4; mt++) {
            const int row = s0 + wm*64 + mt*16 + gid;
            *(__half2*)(dst + (size_t)row * SEQ + col) =
                __floats2half2_rn(c[mt][nt][0], c[mt][nt][1]);
            *(__half2*)(dst + (size_t)(row + 8) * SEQ + col) =
                __floats2half2_rn(c[mt][nt][2], c[mt][nt][3]);
        }
    }
}

// ============================================================
// Kernel 3: fp16 flash attention. P kept in registers (C->A fragment
// reuse); no P smem round-trip.
// ============================================================
#define AHP 72
#define ATT_SMEM_HALVES (2*64*AHP + 2*64*AHP)
#define ATT_SMEM_BYTES (ATT_SMEM_HALVES * 2)   // 36864 B

__global__ __launch_bounds__(256, 2)
void attn_tc_kernel(float* __restrict__ out)
{
    const int qt = gridDim.x - 1 - blockIdx.x;
    const int bh = blockIdx.y;
    const int b = bh >> 4, h = bh & 15;
    const int s0 = qt * 128;

    extern __shared__ __half smh[];
    __half* ks = smh;                    // [2][64][AHP]
    __half* vT = ks + 2*64*AHP;          // [2][64][AHP]

    const int tid = threadIdx.x;
    const int wid = tid >> 5;
    const int lane = tid & 31;
    const int gid = lane >> 2;
    const int tig = lane & 3;
    const int r0 = wid*16 + gid;
    const int r1 = r0 + 8;
    const int sg0 = s0 + r0;
    const int sg1 = s0 + r1;

    const int lmB_row = (lane & 7) + ((lane >> 4) & 1) * 8;
    const int lmB_kof = ((lane >> 3) & 1) * 8;

    const float*  qb  = g_q + ((size_t)b * SEQ + s0) * D_MODEL + (size_t)h * D_HEAD;
    const __half* kb  = g_k + (size_t)b * SEQ * D_MODEL + (size_t)h * D_HEAD;
    const __half* vtb = g_vT + (size_t)bh * D_HEAD * SEQ;
    const __half* qr0 = g_qer + (size_t)bh * SEQ * SEQ + (size_t)sg0 * SEQ;
    const __half* qr1 = g_qer + (size_t)bh * SEQ * SEQ + (size_t)sg1 * SEQ;

    // Q fragments resident in registers
    uint32_t qf[4][4];
#pragma unroll
    for (int k4 = 0; k4 < 4; k4++) {
        const int cc = k4*16 + 2*tig;
        const float2 x0 = *(const float2*)(qb + (size_t)r0 * D_MODEL + cc);
        const float2 x1 = *(const float2*)(qb + (size_t)r1 * D_MODEL + cc);
        const float2 x2 = *(const float2*)(qb + (size_t)r0 * D_MODEL + cc + 8);
        const float2 x3 = *(const float2*)(qb + (size_t)r1 * D_MODEL + cc + 8);
        qf[k4][0] = pack_h2(x0.x, x0.y);
        qf[k4][1] = pack_h2(x1.x, x1.y);
        qf[k4][2] = pack_h2(x2.x, x2.y);
        qf[k4][3] = pack_h2(x3.x, x3.y);
    }

    const uint32_t ks_base = (uint32_t)__cvta_generic_to_shared(ks);
    const uint32_t vt_base = (uint32_t)__cvta_generic_to_shared(vT);
    const int ci0 = tid * 2;
    const int ci1 = tid * 2 + 1;
    const int krow0 = ci0 >> 3, ko0 = (ci0 & 7) * 8;
    const int krow1 = ci1 >> 3, ko1 = (ci1 & 7) * 8;

    float o[8][4];
#pragma unroll
    for (int nt = 0; nt < 8; nt++) { o[nt][0]=0.f; o[nt][1]=0.f; o[nt][2]=0.f; o[nt][3]=0.f; }
    float m0v = -1e30f, m1v = -1e30f, l0v = 0.f, l1v = 0.f;
    const int nkt = 2 * qt + 2;

    // prologue: async-load tile 0 into buffer 0
    {
        cp_async16(ks_base + (krow0*AHP + ko0)*2, kb + (size_t)krow0 * D_MODEL + ko0);
        cp_async16(ks_base + (krow1*AHP + ko1)*2, kb + (size_t)krow1 * D_MODEL + ko1);
        cp_async16(vt_base + (krow0*AHP + ko0)*2, vtb + (size_t)krow0 * SEQ + ko0);
        cp_async16(vt_base + (krow1*AHP + ko1)*2, vtb + (size_t)krow1 * SEQ + ko1);
        CP_COMMIT();
    }

    // seed tile 0 rel bias into s_ (clamped skew gather)
    float s_[8][4];
    {
        const int ja0 = 2047 + 2*tig - sg0;
        const int jb0 = 2047 + 2*tig - sg1;
#pragma unroll
        for (int nt = 0; nt < 8; nt++) {
            int ja = ja0 + nt*8, jb = ja + 1;
            int jc = jb0 + nt*8, jd = jc + 1;
            ja = ja > 2047 ? 2047 : ja;  jb = jb > 2047 ? 2047 : jb;
            jc = jc > 2047 ? 2047 : jc;  jd = jd > 2047 ? 2047 : jd;
            s_[nt][0] = __half2float(qr0[ja]);
            s_[nt][1] = __half2float(qr0[jb]);
            s_[nt][2] = __half2float(qr1[jc]);
            s_[nt][3] = __half2float(qr1[jd]);
        }
    }

    for (int kt = 0; kt < nkt; kt++) {
        const int t0 = kt * 64;
        const int buf = kt & 1;

        CP_WAIT0();
        __syncthreads();

        if (kt + 1 < nkt) {
            const int t0n = t0 + 64;
            const int boff = (buf ^ 1) * 64 * AHP * 2;
            cp_async16(ks_base + boff + (krow0*AHP + ko0)*2, kb + (size_t)(t0n + krow0) * D_MODEL + ko0);
            cp_async16(ks_base + boff + (krow1*AHP + ko1)*2, kb + (size_t)(t0n + krow1) * D_MODEL + ko1);
            cp_async16(vt_base + boff + (krow0*AHP + ko0)*2, vtb + (size_t)krow0 * SEQ + t0n + ko0);
            cp_async16(vt_base + boff + (krow1*AHP + ko1)*2, vtb + (size_t)krow1 * SEQ + t0n + ko1);
        }
        CP_COMMIT();

        const uint32_t ksb_u = ks_base + (uint32_t)(buf * 64 * AHP * 2);
        const uint32_t vtf_u = vt_base + (uint32_t)(buf * 64 * AHP * 2);

        // S += Q K^T
#pragma unroll
        for (int k4 = 0; k4 < 4; k4++) {
            const int kk = k4 * 16;
#pragma unroll
            for (int ntp = 0; ntp < 4; ntp++) {
                uint32_t b00, b01, b10, b11;
                const uint32_t addr = ksb_u +
                    2u * (uint32_t)((ntp*16 + lmB_row) * AHP + kk + lmB_kof);
                ldsm_x4(b00, b01, b10, b11, addr);
                mma_f16(s_[2*ntp][0], s_[2*ntp][1], s_[2*ntp][2], s_[2*ntp][3],
                        qf[k4][0], qf[k4][1], qf[k4][2], qf[k4][3], b00, b01);
                mma_f16(s_[2*ntp+1][0], s_[2*ntp+1][1], s_[2*ntp+1][2], s_[2*ntp+1][3],
                        qf[k4][0], qf[k4][1], qf[k4][2], qf[k4][3], b10, b11);
            }
        }

        // ---- online softmax, row half 0: pack P into s_[nt][0] ----
        {
            float rmax = -1e30f;
#pragma unroll
            for (int nt = 0; nt < 8; nt++) {
                int tc = t0 + nt*8 + 2*tig;
                float v0 = s_[nt][0] * 0.125f;
                float v1 = s_[nt][1] * 0.125f;
                v0 = (tc     <= sg0) ? v0 : -1e30f;
                v1 = (tc + 1 <= sg0) ? v1 : -1e30f;
                s_[nt][0] = v0; s_[nt][1] = v1;
                rmax = fmaxf(rmax, fmaxf(v0, v1));
            }
            rmax = fmaxf(rmax, __shfl_xor_sync(0xffffffffu, rmax, 1));
            rmax = fmaxf(rmax, __shfl_xor_sync(0xffffffffu, rmax, 2));
            float mn = fmaxf(m0v, rmax);
            float alpha = __expf(m0v - mn);
            m0v = mn;
            float lsum = 0.f;
#pragma unroll
            for (int nt = 0; nt < 8; nt++) {
                float p0 = __expf(s_[nt][0] - mn);
                float p1 = __expf(s_[nt][1] - mn);
                lsum += p0 + p1;
                s_[nt][0] = __uint_as_float(pack_h2(p0, p1));
                o[nt][0] *= alpha; o[nt][1] *= alpha;
            }
            lsum += __shfl_xor_sync(0xffffffffu, lsum, 1);
            lsum += __shfl_xor_sync(0xffffffffu, lsum, 2);
            l0v = l0v * alpha + lsum;
        }
        // ---- row half 1: pack P into s_[nt][2] ----
        {
            float rmax = -1e30f;
#pragma unroll
            for (int nt = 0; nt < 8; nt++) {
                int tc = t0 + nt*8 + 2*tig;
                float v0 = s_[nt][2] * 0.125f;
                float v1 = s_[nt][3] * 0.125f;
                v0 = (tc     <= sg1) ? v0 : -1e30f;
                v1 = (tc + 1 <= sg1) ? v1 : -1e30f;
                s_[nt][2] = v0; s_[nt][3] = v1;
                rmax = fmaxf(rmax, fmaxf(v0, v1));
            }
            rmax = fmaxf(rmax, __shfl_xor_sync(0xffffffffu, rmax, 1));
            rmax = fmaxf(rmax, __shfl_xor_sync(0xffffffffu, rmax, 2));
            float mn = fmaxf(m1v, rmax);
            float alpha = __expf(m1v - mn);
            m1v = mn;
            float lsum = 0.f;
#pragma unroll
            for (int nt = 0; nt < 8; nt++) {
                float p0 = __expf(s_[nt][2] - mn);
                float p1 = __expf(s_[nt][3] - mn);
                lsum += p0 + p1;
                s_[nt][2] = __uint_as_float(pack_h2(p0, p1));
                o[nt][2] *= alpha; o[nt][3] *= alpha;
            }
            lsum += __shfl_xor_sync(0xffffffffu, lsum, 1);
            lsum += __shfl_xor_sync(0xffffffffu, lsum, 2);
            l1v = l1v * alpha + lsum;
        }

        // O += P V  -- A fragments come directly from packed s_ (C->A reuse)
#pragma unroll
        for (int k4 = 0; k4 < 4; k4++) {
            const int kk = k4 * 16;
            const uint32_t a0 = __float_as_uint(s_[2*k4][0]);
            const uint32_t a1 = __float_as_uint(s_[2*k4][2]);
            const uint32_t a2 = __float_as_uint(s_[2*k4+1][0]);
            const uint32_t a3 = __float_as_uint(s_[2*k4+1][2]);
#pragma unroll
            for (int ntp = 0; ntp < 4; ntp++) {
                uint32_t b00, b01, b10, b11;
                const uint32_t addr = vtf_u +
                    2u * (uint32_t)((ntp*16 + lmB_row) * AHP + kk + lmB_kof);
                ldsm_x4(b00, b01, b10, b11, addr);
                mma_f16(o[2*ntp][0], o[2*ntp][1], o[2*ntp][2], o[2*ntp][3],
                        a0, a1, a2, a3, b00, b01);
                mma_f16(o[2*ntp+1][0], o[2*ntp+1][1], o[2*ntp+1][2], o[2*ntp+1][3],
                        a0, a1, a2, a3, b10, b11);
            }
        }

        // prefetch next tile's rel-bias seeds into s_ (now fully dead)
        {
            const int t0n = t0 + 64;
            const int ja0 = 2047 + t0n + 2*tig - sg0;
            const int jb0 = 2047 + t0n + 2*tig - sg1;
#pragma unroll
            for (int nt = 0; nt < 8; nt++) {
                int ja = ja0 + nt*8, jb = ja + 1;
                int jc = jb0 + nt*8, jd = jc + 1;
                ja = ja > 2047 ? 2047 : ja;  jb = jb > 2047 ? 2047 : jb;
                jc = jc > 2047 ? 2047 : jc;  jd = jd > 2047 ? 2047 : jd;
                s_[nt][0] = __half2float(qr0[ja]);
                s_[nt][1] = __half2float(qr0[jb]);
                s_[nt][2] = __half2float(qr1[jc]);
                s_[nt][3] = __half2float(qr1[jd]);
            }
        }
    }

    // epilogue
    const float inv0 = 1.f / l0v;
    const float inv1 = 1.f / l1v;
    float* ob = out + (size_t)b * SEQ * D_MODEL + (size_t)h * D_HEAD;
#pragma unroll
    for (int nt = 0; nt < 8; nt++) {
        const int d = nt*8 + 2*tig;
        *(float2*)(ob + (size_t)sg0 * D_MODEL + d) = make_float2(o[nt][0]*inv0, o[nt][1]*inv0);
        *(float2*)(ob + (size_t)sg1 * D_MODEL + d) = make_float2(o[nt][2]*inv1, o[nt][3]*inv1);
    }
}

// ============================================================
// launcher
// ============================================================
extern "C" void kernel_launch(void* const* d_in, const int* in_sizes, int n_in,
                              void* d_out, int out_size)
{
    const float* x  = (const float*)d_in[0];
    const float* Wq = (const float*)d_in[1];
    const float* bq = (const float*)d_in[2];
    const float* Wk = (const float*)d_in[3];
    const float* bk = (const float*)d_in[4];
    const float* Wv = (const float*)d_in[5];
    const float* bv = (const float*)d_in[6];
    const float* Er = (const float*)d_in[7];
    float* out = (float*)d_out;

    cudaFuncSetAttribute(qkv_tc_kernel, cudaFuncAttributeMaxDynamicSharedMemorySize,
                         GEMM_SMEM_BYTES);
    cudaFuncSetAttribute(qer_tc_kernel, cudaFuncAttributeMaxDynamicSharedMemorySize,
                         GEMM_SMEM_BYTES);
    cudaFuncSetAttribute(attn_tc_kernel, cudaFuncAttributeMaxDynamicSharedMemorySize,
                         ATT_SMEM_BYTES);

    // convert x and weights to fp16 once
    {
        const size_t total4 = ((size_t)BATCH*SEQ*D_MODEL + 3*(size_t)D_MODEL*D_MODEL) / 4;
        const int blocks = (int)((total4 + 255) / 256);
        cvt_inputs_kernel<<<blocks, 256>>>(x, Wq, Wk, Wv);
    }

    dim3 g1(D_MODEL / 128, (BATCH * SEQ) / 128, 3);
    qkv_tc_kernel<<<g1, 256, GEMM_SMEM_BYTES>>>(bq, bk, bv);

    dim3 g2(SEQ / 128, SEQ / 128, BHN);
    qer_tc_kernel<<<g2, 256, GEMM_SMEM_BYTES>>>(Er);

    dim3 g3(SEQ / 128, BHN);
    attn_tc_kernel<<<g3, 256, ATT_SMEM_BYTES>>>(out);
}

// round 11
// speedup vs baseline: 1.1067x; 1.1067x over previous
#include <cuda_runtime.h>
#include <cuda_fp16.h>
#include <math.h>
#include <stdint.h>

#define D_MODEL 1024
#define NUM_HEADS 16
#define D_HEAD 64
#define BATCH 2
#define SEQ 2048
#define BHN (BATCH*NUM_HEADS)

// -------- scratch (static device memory; no runtime allocation) --------
__device__ float  g_q  [(size_t)BATCH*SEQ*D_MODEL];          // 16 MB fp32
__device__ __half g_k  [(size_t)BATCH*SEQ*D_MODEL];          // 8 MB fp16
__device__ __half g_vT [(size_t)BHN*D_HEAD*SEQ];             // 8 MB fp16, [bh][d][s]
__device__ __half g_qer[(size_t)BHN*SEQ*SEQ];                // 256 MB fp16

// ---------------- helpers ----------------
__device__ __forceinline__ void mma_f16(float& c0, float& c1, float& c2, float& c3,
                                        uint32_t a0, uint32_t a1, uint32_t a2, uint32_t a3,
                                        uint32_t b0, uint32_t b1) {
    asm volatile(
        "mma.sync.aligned.m16n8k16.row.col.f32.f16.f16.f32 "
        "{%0,%1,%2,%3}, {%4,%5,%6,%7}, {%8,%9}, {%0,%1,%2,%3};"
        : "+f"(c0), "+f"(c1), "+f"(c2), "+f"(c3)
        : "r"(a0), "r"(a1), "r"(a2), "r"(a3), "r"(b0), "r"(b1));
}
__device__ __forceinline__ void ldsm_x4(uint32_t& r0, uint32_t& r1, uint32_t& r2, uint32_t& r3,
                                        uint32_t saddr) {
    asm volatile("ldmatrix.sync.aligned.m8n8.x4.shared.b16 {%0,%1,%2,%3}, [%4];"
                 : "=r"(r0), "=r"(r1), "=r"(r2), "=r"(r3) : "r"(saddr));
}
__device__ __forceinline__ uint32_t pack_h2(float x, float y) {
    __half2 h = __floats2half2_rn(x, y);
    return *(uint32_t*)&h;
}
__device__ __forceinline__ void cp_async16(uint32_t saddr, const void* g) {
    asm volatile("cp.async.cg.shared.global [%0], [%1], 16;" :: "r"(saddr), "l"(g));
}
#define CP_COMMIT() asm volatile("cp.async.commit_group;")
#define CP_WAIT0()  asm volatile("cp.async.wait_group 0;")

// smem geometry for fp16 tensor-core GEMMs: [2 buf][128 rows][HP] halves
#define HP 40
#define GEMM_SMEM_BYTES (2*128*HP*2*2)   // A + B -> 40960 B

// ============================================================
// Kernel 1 (fp16 tensor core): Q/K/V projection.
// Round-9 form: fp32 LDG register-staged -> cvt -> STS, ldmatrix frags.
// ============================================================
__global__ __launch_bounds__(256, 2)
void qkv_tc_kernel(const float* __restrict__ x,
                   const float* __restrict__ Wq, const float* __restrict__ bq,
                   const float* __restrict__ Wk, const float* __restrict__ bk,
                   const float* __restrict__ Wv, const float* __restrict__ bv)
{
    const float* W; const float* bias;
    if (blockIdx.z == 0)      { W = Wq; bias = bq; }
    else if (blockIdx.z == 1) { W = Wk; bias = bk; }
    else                      { W = Wv; bias = bv; }

    extern __shared__ __half smh[];
    __half* As = smh;                // [2][128][HP]
    __half* Bs = smh + 2*128*HP;     // [2][128][HP]
    const uint32_t As_u = (uint32_t)__cvta_generic_to_shared(As);
    const uint32_t Bs_u = (uint32_t)__cvta_generic_to_shared(Bs);

    const int m0 = blockIdx.y * 128;
    const int n0 = blockIdx.x * 128;
    const int tid = threadIdx.x;
    const int wid = tid >> 5;
    const int lane = tid & 31;
    const int gid = lane >> 2;
    const int tig = lane & 3;
    const int wm = wid >> 2;
    const int wn = wid & 3;

    const int lmA_row = (lane & 7) + ((lane >> 3) & 1) * 8;
    const int lmA_kof = ((lane >> 4) & 1) * 8;
    const int lmB_row = (lane & 7) + ((lane >> 4) & 1) * 8;
    const int lmB_kof = ((lane >> 3) & 1) * 8;

    const float* Ag = x + (size_t)m0 * D_MODEL;
    const float* Bg = W + (size_t)n0 * D_MODEL;

    float c[4][4][4];
#pragma unroll
    for (int mt = 0; mt < 4; mt++)
#pragma unroll
        for (int nt = 0; nt < 4; nt++)
#pragma unroll
            for (int r = 0; r < 4; r++) c[mt][nt][r] = 0.f;

    const int lrow = tid >> 3;
    const int lc4  = (tid & 7) * 4;

    float4 pa[4], pb[4];
#pragma unroll
    for (int i = 0; i < 4; i++) {
        pa[i] = *(const float4*)(Ag + (size_t)(lrow + i*32) * D_MODEL + lc4);
        pb[i] = *(const float4*)(Bg + (size_t)(lrow + i*32) * D_MODEL + lc4);
    }
#pragma unroll
    for (int i = 0; i < 4; i++) {
        __half* da = As + (lrow + i*32) * HP + lc4;
        *(uint32_t*)da       = pack_h2(pa[i].x, pa[i].y);
        *(uint32_t*)(da + 2) = pack_h2(pa[i].z, pa[i].w);
        __half* db = Bs + (lrow + i*32) * HP + lc4;
        *(uint32_t*)db       = pack_h2(pb[i].x, pb[i].y);
        *(uint32_t*)(db + 2) = pack_h2(pb[i].z, pb[i].w);
    }
    __syncthreads();

    for (int k0 = 0; k0 < D_MODEL; k0 += 32) {
        const int buf = (k0 >> 5) & 1;
        const bool has_next = (k0 + 32) < D_MODEL;
        if (has_next) {
#pragma unroll
            for (int i = 0; i < 4; i++) {
                pa[i] = *(const float4*)(Ag + (size_t)(lrow + i*32) * D_MODEL + k0 + 32 + lc4);
                pb[i] = *(const float4*)(Bg + (size_t)(lrow + i*32) * D_MODEL + k0 + 32 + lc4);
            }
        }
#pragma unroll
        for (int ks = 0; ks < 2; ks++) {
            const int kk = ks * 16;
            uint32_t a[4][4];
#pragma unroll
            for (int mt = 0; mt < 4; mt++) {
                const uint32_t addr = As_u +
                    2u * (uint32_t)((buf*128 + wm*64 + mt*16 + lmA_row) * HP + kk + lmA_kof);
                ldsm_x4(a[mt][0], a[mt][1], a[mt][2], a[mt][3], addr);
            }
#pragma unroll
            for (int ntp = 0; ntp < 2; ntp++) {
                uint32_t b00, b01, b10, b11;
                const uint32_t addr = Bs_u +
                    2u * (uint32_t)((buf*128 + wn*32 + ntp*16 + lmB_row) * HP + kk + lmB_kof);
                ldsm_x4(b00, b01, b10, b11, addr);
#pragma unroll
                for (int mt = 0; mt < 4; mt++) {
                    mma_f16(c[mt][2*ntp][0], c[mt][2*ntp][1], c[mt][2*ntp][2], c[mt][2*ntp][3],
                            a[mt][0], a[mt][1], a[mt][2], a[mt][3], b00, b01);
                    mma_f16(c[mt][2*ntp+1][0], c[mt][2*ntp+1][1], c[mt][2*ntp+1][2], c[mt][2*ntp+1][3],
                            a[mt][0], a[mt][1], a[mt][2], a[mt][3], b10, b11);
                }
            }
        }
        if (has_next) {
            const int nb = buf ^ 1;
#pragma unroll
            for (int i = 0; i < 4; i++) {
                __half* da = As + nb*128*HP + (lrow + i*32) * HP + lc4;
                *(uint32_t*)da       = pack_h2(pa[i].x, pa[i].y);
                *(uint32_t*)(da + 2) = pack_h2(pa[i].z, pa[i].w);
                __half* db = Bs + nb*128*HP + (lrow + i*32) * HP + lc4;
                *(uint32_t*)db       = pack_h2(pb[i].x, pb[i].y);
                *(uint32_t*)(db + 2) = pack_h2(pb[i].z, pb[i].w);
            }
            __syncthreads();
        }
    }

    if (blockIdx.z == 0) {
#pragma unroll
        for (int nt = 0; nt < 4; nt++) {
            const int col = n0 + wn*32 + nt*8 + 2*tig;
            const float2 bb = *(const float2*)(bias + col);
#pragma unroll
            for (int mt = 0; mt < 4; mt++) {
                const int row = m0 + wm*64 + mt*16 + gid;
                *(float2*)(g_q + (size_t)row * D_MODEL + col) =
                    make_float2(c[mt][nt][0] + bb.x, c[mt][nt][1] + bb.y);
                *(float2*)(g_q + (size_t)(row + 8) * D_MODEL + col) =
                    make_float2(c[mt][nt][2] + bb.x, c[mt][nt][3] + bb.y);
            }
        }
    } else if (blockIdx.z == 1) {
#pragma unroll
        for (int nt = 0; nt < 4; nt++) {
            const int col = n0 + wn*32 + nt*8 + 2*tig;
            const float2 bb = *(const float2*)(bias + col);
#pragma unroll
            for (int mt = 0; mt < 4; mt++) {
                const int row = m0 + wm*64 + mt*16 + gid;
                *(__half2*)(g_k + (size_t)row * D_MODEL + col) =
                    __floats2half2_rn(c[mt][nt][0] + bb.x, c[mt][nt][1] + bb.y);
                *(__half2*)(g_k + (size_t)(row + 8) * D_MODEL + col) =
                    __floats2half2_rn(c[mt][nt][2] + bb.x, c[mt][nt][3] + bb.y);
            }
        }
    } else {
#pragma unroll
        for (int nt = 0; nt < 4; nt++) {
            const int col = n0 + wn*32 + nt*8 + 2*tig;
            const float2 bb = *(const float2*)(bias + col);
            const int hh = col >> 6;
            const int d0 = col & 63;
#pragma unroll
            for (int mt = 0; mt < 4; mt++) {
                const int row = m0 + wm*64 + mt*16 + gid;
                const int bidx = row >> 11;
                const int sidx = row & 2047;
                __half* base = g_vT + ((size_t)(bidx*NUM_HEADS + hh) * D_HEAD + d0) * SEQ;
                base[sidx]            = __float2half(c[mt][nt][0] + bb.x);
                base[SEQ + sidx]      = __float2half(c[mt][nt][1] + bb.y);
                base[sidx + 8]        = __float2half(c[mt][nt][2] + bb.x);
                base[SEQ + sidx + 8]  = __float2half(c[mt][nt][3] + bb.y);
            }
        }
    }
}

// ============================================================
// Kernel 2 (fp16 tensor core): QEr[bh][s][j] = q_head[s,:] . Er[j,:]
// ============================================================
__global__ __launch_bounds__(256, 2)
void qer_tc_kernel(const float* __restrict__ Er)
{
    const int bh = blockIdx.z;
    const int b = bh >> 4, h = bh & 15;
    const int j0 = blockIdx.x * 128;
    const int s0 = blockIdx.y * 128;
    if (s0 + j0 + 254 < SEQ - 1) return;

    extern __shared__ __half smh[];
    __half* As = smh;
    __half* Bs = smh + 2*128*HP;
    const uint32_t As_u = (uint32_t)__cvta_generic_to_shared(As);
    const uint32_t Bs_u = (uint32_t)__cvta_generic_to_shared(Bs);

    const int tid = threadIdx.x;
    const int wid = tid >> 5;
    const int lane = tid & 31;
    const int gid = lane >> 2;
    const int tig = lane & 3;
    const int wm = wid >> 2;
    const int wn = wid & 3;

    const int lmA_row = (lane & 7) + ((lane >> 3) & 1) * 8;
    const int lmA_kof = ((lane >> 4) & 1) * 8;
    const int lmB_row = (lane & 7) + ((lane >> 4) & 1) * 8;
    const int lmB_kof = ((lane >> 3) & 1) * 8;

    const float* Ag = g_q + ((size_t)b * SEQ + s0) * D_MODEL + (size_t)h * D_HEAD;
    const float* Bg = Er + (size_t)j0 * D_HEAD;

    float c[4][4][4];
#pragma unroll
    for (int mt = 0; mt < 4; mt++)
#pragma unroll
        for (int nt = 0; nt < 4; nt++)
#pragma unroll
            for (int r = 0; r < 4; r++) c[mt][nt][r] = 0.f;

    const int lrow = tid >> 3;
    const int lc4  = (tid & 7) * 4;

    float4 pa[4], pb[4];
#pragma unroll
    for (int i = 0; i < 4; i++) {
        pa[i] = *(const float4*)(Ag + (size_t)(lrow + i*32) * D_MODEL + lc4);
        pb[i] = *(const float4*)(Bg + (size_t)(lrow + i*32) * D_HEAD + lc4);
    }
#pragma unroll
    for (int i = 0; i < 4; i++) {
        __half* da = As + (lrow + i*32) * HP + lc4;
        *(uint32_t*)da       = pack_h2(pa[i].x, pa[i].y);
        *(uint32_t*)(da + 2) = pack_h2(pa[i].z, pa[i].w);
        __half* db = Bs + (lrow + i*32) * HP + lc4;
        *(uint32_t*)db       = pack_h2(pb[i].x, pb[i].y);
        *(uint32_t*)(db + 2) = pack_h2(pb[i].z, pb[i].w);
    }
    __syncthreads();

    for (int k0 = 0; k0 < D_HEAD; k0 += 32) {
        const int buf = (k0 >> 5) & 1;
        const bool has_next = (k0 + 32) < D_HEAD;
        if (has_next) {
#pragma unroll
            for (int i = 0; i < 4; i++) {
                pa[i] = *(const float4*)(Ag + (size_t)(lrow + i*32) * D_MODEL + k0 + 32 + lc4);
                pb[i] = *(const float4*)(Bg + (size_t)(lrow + i*32) * D_HEAD + k0 + 32 + lc4);
            }
        }
#pragma unroll
        for (int ks = 0; ks < 2; ks++) {
            const int kk = ks * 16;
            uint32_t a[4][4];
#pragma unroll
            for (int mt = 0; mt < 4; mt++) {
                const uint32_t addr = As_u +
                    2u * (uint32_t)((buf*128 + wm*64 + mt*16 + lmA_row) * HP + kk + lmA_kof);
                ldsm_x4(a[mt][0], a[mt][1], a[mt][2], a[mt][3], addr);
            }
#pragma unroll
            for (int ntp = 0; ntp < 2; ntp++) {
                uint32_t b00, b01, b10, b11;
                const uint32_t addr = Bs_u +
                    2u * (uint32_t)((buf*128 + wn*32 + ntp*16 + lmB_row) * HP + kk + lmB_kof);
                ldsm_x4(b00, b01, b10, b11, addr);
#pragma unroll
                for (int mt = 0; mt < 4; mt++) {
                    mma_f16(c[mt][2*ntp][0], c[mt][2*ntp][1], c[mt][2*ntp][2], c[mt][2*ntp][3],
                            a[mt][0], a[mt][1], a[mt][2], a[mt][3], b00, b01);
                    mma_f16(c[mt][2*ntp+1][0], c[mt][2*ntp+1][1], c[mt][2*ntp+1][2], c[mt][2*ntp+1][3],
                            a[mt][0], a[mt][1], a[mt][2], a[mt][3], b10, b11);
                }
            }
        }
        if (has_next) {
            const int nb = buf ^ 1;
#pragma unroll
            for (int i = 0; i < 4; i++) {
                __half* da = As + nb*128*HP + (lrow + i*32) * HP + lc4;
                *(uint32_t*)da       = pack_h2(pa[i].x, pa[i].y);
                *(uint32_t*)(da + 2) = pack_h2(pa[i].z, pa[i].w);
                __half* db = Bs + nb*128*HP + (lrow + i*32) * HP + lc4;
                *(uint32_t*)db       = pack_h2(pb[i].x, pb[i].y);
                *(uint32_t*)(db + 2) = pack_h2(pb[i].z, pb[i].w);
            }
            __syncthreads();
        }
    }

    __half* dst = g_qer + (size_t)bh * SEQ * SEQ;
#pragma unroll
    for (int nt = 0; nt < 4; nt++) {
        const int col = j0 + wn*32 + nt*8 + 2*tig;
#pragma unroll
        for (int mt = 0; mt < 4; mt++) {
            const int row = s0 + wm*64 + mt*16 + gid;
            *(__half2*)(dst + (size_t)row * SEQ + col) =
                __floats2half2_rn(c[mt][nt][0], c[mt][nt][1]);
            *(__half2*)(dst + (size_t)(row + 8) * SEQ + col) =
                __floats2half2_rn(c[mt][nt][2], c[mt][nt][3]);
        }
    }
}

// ============================================================
// Kernel 3: fp16 flash attention. P kept in registers (C->A fragment
// reuse); no P smem round-trip.  (Round-10 version, confirmed 184us.)
// ============================================================
#define AHP 72
#define ATT_SMEM_HALVES (2*64*AHP + 2*64*AHP)
#define ATT_SMEM_BYTES (ATT_SMEM_HALVES * 2)   // 36864 B

__global__ __launch_bounds__(256, 2)
void attn_tc_kernel(float* __restrict__ out)
{
    const int qt = gridDim.x - 1 - blockIdx.x;
    const int bh = blockIdx.y;
    const int b = bh >> 4, h = bh & 15;
    const int s0 = qt * 128;

    extern __shared__ __half smh[];
    __half* ks = smh;                    // [2][64][AHP]
    __half* vT = ks + 2*64*AHP;          // [2][64][AHP]

    const int tid = threadIdx.x;
    const int wid = tid >> 5;
    const int lane = tid & 31;
    const int gid = lane >> 2;
    const int tig = lane & 3;
    const int r0 = wid*16 + gid;
    const int r1 = r0 + 8;
    const int sg0 = s0 + r0;
    const int sg1 = s0 + r1;

    const int lmB_row = (lane & 7) + ((lane >> 4) & 1) * 8;
    const int lmB_kof = ((lane >> 3) & 1) * 8;

    const float*  qb  = g_q + ((size_t)b * SEQ + s0) * D_MODEL + (size_t)h * D_HEAD;
    const __half* kb  = g_k + (size_t)b * SEQ * D_MODEL + (size_t)h * D_HEAD;
    const __half* vtb = g_vT + (size_t)bh * D_HEAD * SEQ;
    const __half* qr0 = g_qer + (size_t)bh * SEQ * SEQ + (size_t)sg0 * SEQ;
    const __half* qr1 = g_qer + (size_t)bh * SEQ * SEQ + (size_t)sg1 * SEQ;

    // Q fragments resident in registers
    uint32_t qf[4][4];
#pragma unroll
    for (int k4 = 0; k4 < 4; k4++) {
        const int cc = k4*16 + 2*tig;
        const float2 x0 = *(const float2*)(qb + (size_t)r0 * D_MODEL + cc);
        const float2 x1 = *(const float2*)(qb + (size_t)r1 * D_MODEL + cc);
        const float2 x2 = *(const float2*)(qb + (size_t)r0 * D_MODEL + cc + 8);
        const float2 x3 = *(const float2*)(qb + (size_t)r1 * D_MODEL + cc + 8);
        qf[k4][0] = pack_h2(x0.x, x0.y);
        qf[k4][1] = pack_h2(x1.x, x1.y);
        qf[k4][2] = pack_h2(x2.x, x2.y);
        qf[k4][3] = pack_h2(x3.x, x3.y);
    }

    const uint32_t ks_base = (uint32_t)__cvta_generic_to_shared(ks);
    const uint32_t vt_base = (uint32_t)__cvta_generic_to_shared(vT);
    const int ci0 = tid * 2;
    const int ci1 = tid * 2 + 1;
    const int krow0 = ci0 >> 3, ko0 = (ci0 & 7) * 8;
    const int krow1 = ci1 >> 3, ko1 = (ci1 & 7) * 8;

    float o[8][4];
#pragma unroll
    for (int nt = 0; nt < 8; nt++) { o[nt][0]=0.f; o[nt][1]=0.f; o[nt][2]=0.f; o[nt][3]=0.f; }
    float m0v = -1e30f, m1v = -1e30f, l0v = 0.f, l1v = 0.f;
    const int nkt = 2 * qt + 2;

    // prologue: async-load tile 0 into buffer 0
    {
        cp_async16(ks_base + (krow0*AHP + ko0)*2, kb + (size_t)krow0 * D_MODEL + ko0);
        cp_async16(ks_base + (krow1*AHP + ko1)*2, kb + (size_t)krow1 * D_MODEL + ko1);
        cp_async16(vt_base + (krow0*AHP + ko0)*2, vtb + (size_t)krow0 * SEQ + ko0);
        cp_async16(vt_base + (krow1*AHP + ko1)*2, vtb + (size_t)krow1 * SEQ + ko1);
        CP_COMMIT();
    }

    // seed tile 0 rel bias into s_ (clamped skew gather)
    float s_[8][4];
    {
        const int ja0 = 2047 + 2*tig - sg0;
        const int jb0 = 2047 + 2*tig - sg1;
#pragma unroll
        for (int nt = 0; nt < 8; nt++) {
            int ja = ja0 + nt*8, jb = ja + 1;
            int jc = jb0 + nt*8, jd = jc + 1;
            ja = ja > 2047 ? 2047 : ja;  jb = jb > 2047 ? 2047 : jb;
            jc = jc > 2047 ? 2047 : jc;  jd = jd > 2047 ? 2047 : jd;
            s_[nt][0] = __half2float(qr0[ja]);
            s_[nt][1] = __half2float(qr0[jb]);
            s_[nt][2] = __half2float(qr1[jc]);
            s_[nt][3] = __half2float(qr1[jd]);
        }
    }

    for (int kt = 0; kt < nkt; kt++) {
        const int t0 = kt * 64;
        const int buf = kt & 1;

        CP_WAIT0();
        __syncthreads();

        if (kt + 1 < nkt) {
            const int t0n = t0 + 64;
            const int boff = (buf ^ 1) * 64 * AHP * 2;
            cp_async16(ks_base + boff + (krow0*AHP + ko0)*2, kb + (size_t)(t0n + krow0) * D_MODEL + ko0);
            cp_async16(ks_base + boff + (krow1*AHP + ko1)*2, kb + (size_t)(t0n + krow1) * D_MODEL + ko1);
            cp_async16(vt_base + boff + (krow0*AHP + ko0)*2, vtb + (size_t)krow0 * SEQ + t0n + ko0);
            cp_async16(vt_base + boff + (krow1*AHP + ko1)*2, vtb + (size_t)krow1 * SEQ + t0n + ko1);
        }
        CP_COMMIT();

        const uint32_t ksb_u = ks_base + (uint32_t)(buf * 64 * AHP * 2);
        const uint32_t vtf_u = vt_base + (uint32_t)(buf * 64 * AHP * 2);

        // S += Q K^T
#pragma unroll
        for (int k4 = 0; k4 < 4; k4++) {
            const int kk = k4 * 16;
#pragma unroll
            for (int ntp = 0; ntp < 4; ntp++) {
                uint32_t b00, b01, b10, b11;
                const uint32_t addr = ksb_u +
                    2u * (uint32_t)((ntp*16 + lmB_row) * AHP + kk + lmB_kof);
                ldsm_x4(b00, b01, b10, b11, addr);
                mma_f16(s_[2*ntp][0], s_[2*ntp][1], s_[2*ntp][2], s_[2*ntp][3],
                        qf[k4][0], qf[k4][1], qf[k4][2], qf[k4][3], b00, b01);
                mma_f16(s_[2*ntp+1][0], s_[2*ntp+1][1], s_[2*ntp+1][2], s_[2*ntp+1][3],
                        qf[k4][0], qf[k4][1], qf[k4][2], qf[k4][3], b10, b11);
            }
        }

        // ---- online softmax, row half 0: pack P into s_[nt][0] ----
        {
            float rmax = -1e30f;
#pragma unroll
            for (int nt = 0; nt < 8; nt++) {
                int tc = t0 + nt*8 + 2*tig;
                float v0 = s_[nt][0] * 0.125f;
                float v1 = s_[nt][1] * 0.125f;
                v0 = (tc     <= sg0) ? v0 : -1e30f;
                v1 = (tc + 1 <= sg0) ? v1 : -1e30f;
                s_[nt][0] = v0; s_[nt][1] = v1;
                rmax = fmaxf(rmax, fmaxf(v0, v1));
            }
            rmax = fmaxf(rmax, __shfl_xor_sync(0xffffffffu, rmax, 1));
            rmax = fmaxf(rmax, __shfl_xor_sync(0xffffffffu, rmax, 2));
            float mn = fmaxf(m0v, rmax);
            float alpha = __expf(m0v - mn);
            m0v = mn;
            float lsum = 0.f;
#pragma unroll
            for (int nt = 0; nt < 8; nt++) {
                float p0 = __expf(s_[nt][0] - mn);
                float p1 = __expf(s_[nt][1] - mn);
                lsum += p0 + p1;
                s_[nt][0] = __uint_as_float(pack_h2(p0, p1));
                o[nt][0] *= alpha; o[nt][1] *= alpha;
            }
            lsum += __shfl_xor_sync(0xffffffffu, lsum, 1);
            lsum += __shfl_xor_sync(0xffffffffu, lsum, 2);
            l0v = l0v * alpha + lsum;
        }
        // ---- row half 1: pack P into s_[nt][2] ----
        {
            float rmax = -1e30f;
#pragma unroll
            for (int nt = 0; nt < 8; nt++) {
                int tc = t0 + nt*8 + 2*tig;
                float v0 = s_[nt][2] * 0.125f;
                float v1 = s_[nt][3] * 0.125f;
                v0 = (tc     <= sg1) ? v0 : -1e30f;
                v1 = (tc + 1 <= sg1) ? v1 : -1e30f;
                s_[nt][2] = v0; s_[nt][3] = v1;
                rmax = fmaxf(rmax, fmaxf(v0, v1));
            }
            rmax = fmaxf(rmax, __shfl_xor_sync(0xffffffffu, rmax, 1));
            rmax = fmaxf(rmax, __shfl_xor_sync(0xffffffffu, rmax, 2));
            float mn = fmaxf(m1v, rmax);
            float alpha = __expf(m1v - mn);
            m1v = mn;
            float lsum = 0.f;
#pragma unroll
            for (int nt = 0; nt < 8; nt++) {
                float p0 = __expf(s_[nt][2] - mn);
                float p1 = __expf(s_[nt][3] - mn);
                lsum += p0 + p1;
                s_[nt][2] = __uint_as_float(pack_h2(p0, p1));
                o[nt][2] *= alpha; o[nt][3] *= alpha;
            }
            lsum += __shfl_xor_sync(0xffffffffu, lsum, 1);
            lsum += __shfl_xor_sync(0xffffffffu, lsum, 2);
            l1v = l1v * alpha + lsum;
        }

        // O += P V  -- A fragments come directly from packed s_ (C->A reuse)
#pragma unroll
        for (int k4 = 0; k4 < 4; k4++) {
            const int kk = k4 * 16;
            const uint32_t a0 = __float_as_uint(s_[2*k4][0]);
            const uint32_t a1 = __float_as_uint(s_[2*k4][2]);
            const uint32_t a2 = __float_as_uint(s_[2*k4+1][0]);
            const uint32_t a3 = __float_as_uint(s_[2*k4+1][2]);
#pragma unroll
            for (int ntp = 0; ntp < 4; ntp++) {
                uint32_t b00, b01, b10, b11;
                const uint32_t addr = vtf_u +
                    2u * (uint32_t)((ntp*16 + lmB_row) * AHP + kk + lmB_kof);
                ldsm_x4(b00, b01, b10, b11, addr);
                mma_f16(o[2*ntp][0], o[2*ntp][1], o[2*ntp][2], o[2*ntp][3],
                        a0, a1, a2, a3, b00, b01);
                mma_f16(o[2*ntp+1][0], o[2*ntp+1][1], o[2*ntp+1][2], o[2*ntp+1][3],
                        a0, a1, a2, a3, b10, b11);
            }
        }

        // prefetch next tile's rel-bias seeds into s_ (now fully dead)
        {
            const int t0n = t0 + 64;
            const int ja0 = 2047 + t0n + 2*tig - sg0;
            const int jb0 = 2047 + t0n + 2*tig - sg1;
#pragma unroll
            for (int nt = 0; nt < 8; nt++) {
                int ja = ja0 + nt*8, jb = ja + 1;
                int jc = jb0 + nt*8, jd = jc + 1;
                ja = ja > 2047 ? 2047 : ja;  jb = jb > 2047 ? 2047 : jb;
                jc = jc > 2047 ? 2047 : jc;  jd = jd > 2047 ? 2047 : jd;
                s_[nt][0] = __half2float(qr0[ja]);
                s_[nt][1] = __half2float(qr0[jb]);
                s_[nt][2] = __half2float(qr1[jc]);
                s_[nt][3] = __half2float(qr1[jd]);
            }
        }
    }

    // epilogue
    const float inv0 = 1.f / l0v;
    const float inv1 = 1.f / l1v;
    float* ob = out + (size_t)b * SEQ * D_MODEL + (size_t)h * D_HEAD;
#pragma unroll
    for (int nt = 0; nt < 8; nt++) {
        const int d = nt*8 + 2*tig;
        *(float2*)(ob + (size_t)sg0 * D_MODEL + d) = make_float2(o[nt][0]*inv0, o[nt][1]*inv0);
        *(float2*)(ob + (size_t)sg1 * D_MODEL + d) = make_float2(o[nt][2]*inv1, o[nt][3]*inv1);
    }
}

// ============================================================
// launcher
// ============================================================
extern "C" void kernel_launch(void* const* d_in, const int* in_sizes, int n_in,
                              void* d_out, int out_size)
{
    const float* x  = (const float*)d_in[0];
    const float* Wq = (const float*)d_in[1];
    const float* bq = (const float*)d_in[2];
    const float* Wk = (const float*)d_in[3];
    const float* bk = (const float*)d_in[4];
    const float* Wv = (const float*)d_in[5];
    const float* bv = (const float*)d_in[6];
    const float* Er = (const float*)d_in[7];
    float* out = (float*)d_out;

    cudaFuncSetAttribute(qkv_tc_kernel, cudaFuncAttributeMaxDynamicSharedMemorySize,
                         GEMM_SMEM_BYTES);
    cudaFuncSetAttribute(qer_tc_kernel, cudaFuncAttributeMaxDynamicSharedMemorySize,
                         GEMM_SMEM_BYTES);
    cudaFuncSetAttribute(attn_tc_kernel, cudaFuncAttributeMaxDynamicSharedMemorySize,
                         ATT_SMEM_BYTES);

    dim3 g1(D_MODEL / 128, (BATCH * SEQ) / 128, 3);
    qkv_tc_kernel<<<g1, 256, GEMM_SMEM_BYTES>>>(x, Wq, bq, Wk, bk, Wv, bv);

    dim3 g2(SEQ / 128, SEQ / 128, BHN);
    qer_tc_kernel<<<g2, 256, GEMM_SMEM_BYTES>>>(Er);

    dim3 g3(SEQ / 128, BHN);
    attn_tc_kernel<<<g3, 256, ATT_SMEM_BYTES>>>(out);
}

// round 12
// speedup vs baseline: 1.1189x; 1.0110x over previous
#include <cuda_runtime.h>
#include <cuda_fp16.h>
#include <math.h>
#include <stdint.h>

#define D_MODEL 1024
#define NUM_HEADS 16
#define D_HEAD 64
#define BATCH 2
#define SEQ 2048
#define BHN (BATCH*NUM_HEADS)
#define QER_RS 2056   // padded row stride (halves); keeps 16B alignment

// -------- scratch (static device memory; no runtime allocation) --------
__device__ float  g_q  [(size_t)BATCH*SEQ*D_MODEL];          // 16 MB fp32
__device__ __half g_k  [(size_t)BATCH*SEQ*D_MODEL];          // 8 MB fp16
__device__ __half g_vT [(size_t)BHN*D_HEAD*SEQ];             // 8 MB fp16, [bh][d][s]
// row s stored shifted by delta(s) = 1-(s&1) so skew reads are u32-aligned
__device__ __half g_qer[(size_t)BHN*SEQ*QER_RS + 128];       // ~269 MB fp16

// ---------------- helpers ----------------
__device__ __forceinline__ void mma_f16(float& c0, float& c1, float& c2, float& c3,
                                        uint32_t a0, uint32_t a1, uint32_t a2, uint32_t a3,
                                        uint32_t b0, uint32_t b1) {
    asm volatile(
        "mma.sync.aligned.m16n8k16.row.col.f32.f16.f16.f32 "
        "{%0,%1,%2,%3}, {%4,%5,%6,%7}, {%8,%9}, {%0,%1,%2,%3};"
        : "+f"(c0), "+f"(c1), "+f"(c2), "+f"(c3)
        : "r"(a0), "r"(a1), "r"(a2), "r"(a3), "r"(b0), "r"(b1));
}
__device__ __forceinline__ void ldsm_x4(uint32_t& r0, uint32_t& r1, uint32_t& r2, uint32_t& r3,
                                        uint32_t saddr) {
    asm volatile("ldmatrix.sync.aligned.m8n8.x4.shared.b16 {%0,%1,%2,%3}, [%4];"
                 : "=r"(r0), "=r"(r1), "=r"(r2), "=r"(r3) : "r"(saddr));
}
__device__ __forceinline__ uint32_t pack_h2(float x, float y) {
    __half2 h = __floats2half2_rn(x, y);
    return *(uint32_t*)&h;
}
__device__ __forceinline__ void cp_async16(uint32_t saddr, const void* g) {
    asm volatile("cp.async.cg.shared.global [%0], [%1], 16;" :: "r"(saddr), "l"(g));
}
#define CP_COMMIT() asm volatile("cp.async.commit_group;")
#define CP_WAIT0()  asm volatile("cp.async.wait_group 0;")

// smem geometry for fp16 tensor-core GEMMs: [2 buf][128 rows][HP] halves
#define HP 40
#define GEMM_SMEM_BYTES (2*128*HP*2*2)   // A + B -> 40960 B

// ============================================================
// Kernel 1 (fp16 tensor core): Q/K/V projection.
// ============================================================
__global__ __launch_bounds__(256, 2)
void qkv_tc_kernel(const float* __restrict__ x,
                   const float* __restrict__ Wq, const float* __restrict__ bq,
                   const float* __restrict__ Wk, const float* __restrict__ bk,
                   const float* __restrict__ Wv, const float* __restrict__ bv)
{
    const float* W; const float* bias;
    if (blockIdx.z == 0)      { W = Wq; bias = bq; }
    else if (blockIdx.z == 1) { W = Wk; bias = bk; }
    else                      { W = Wv; bias = bv; }

    extern __shared__ __half smh[];
    __half* As = smh;                // [2][128][HP]
    __half* Bs = smh + 2*128*HP;     // [2][128][HP]
    const uint32_t As_u = (uint32_t)__cvta_generic_to_shared(As);
    const uint32_t Bs_u = (uint32_t)__cvta_generic_to_shared(Bs);

    const int m0 = blockIdx.y * 128;
    const int n0 = blockIdx.x * 128;
    const int tid = threadIdx.x;
    const int wid = tid >> 5;
    const int lane = tid & 31;
    const int gid = lane >> 2;
    const int tig = lane & 3;
    const int wm = wid >> 2;
    const int wn = wid & 3;

    const int lmA_row = (lane & 7) + ((lane >> 3) & 1) * 8;
    const int lmA_kof = ((lane >> 4) & 1) * 8;
    const int lmB_row = (lane & 7) + ((lane >> 4) & 1) * 8;
    const int lmB_kof = ((lane >> 3) & 1) * 8;

    const float* Ag = x + (size_t)m0 * D_MODEL;
    const float* Bg = W + (size_t)n0 * D_MODEL;

    float c[4][4][4];
#pragma unroll
    for (int mt = 0; mt < 4; mt++)
#pragma unroll
        for (int nt = 0; nt < 4; nt++)
#pragma unroll
            for (int r = 0; r < 4; r++) c[mt][nt][r] = 0.f;

    const int lrow = tid >> 3;
    const int lc4  = (tid & 7) * 4;

    float4 pa[4], pb[4];
#pragma unroll
    for (int i = 0; i < 4; i++) {
        pa[i] = *(const float4*)(Ag + (size_t)(lrow + i*32) * D_MODEL + lc4);
        pb[i] = *(const float4*)(Bg + (size_t)(lrow + i*32) * D_MODEL + lc4);
    }
#pragma unroll
    for (int i = 0; i < 4; i++) {
        __half* da = As + (lrow + i*32) * HP + lc4;
        *(uint32_t*)da       = pack_h2(pa[i].x, pa[i].y);
        *(uint32_t*)(da + 2) = pack_h2(pa[i].z, pa[i].w);
        __half* db = Bs + (lrow + i*32) * HP + lc4;
        *(uint32_t*)db       = pack_h2(pb[i].x, pb[i].y);
        *(uint32_t*)(db + 2) = pack_h2(pb[i].z, pb[i].w);
    }
    __syncthreads();

    for (int k0 = 0; k0 < D_MODEL; k0 += 32) {
        const int buf = (k0 >> 5) & 1;
        const bool has_next = (k0 + 32) < D_MODEL;
        if (has_next) {
#pragma unroll
            for (int i = 0; i < 4; i++) {
                pa[i] = *(const float4*)(Ag + (size_t)(lrow + i*32) * D_MODEL + k0 + 32 + lc4);
                pb[i] = *(const float4*)(Bg + (size_t)(lrow + i*32) * D_MODEL + k0 + 32 + lc4);
            }
        }
#pragma unroll
        for (int ks = 0; ks < 2; ks++) {
            const int kk = ks * 16;
            uint32_t a[4][4];
#pragma unroll
            for (int mt = 0; mt < 4; mt++) {
                const uint32_t addr = As_u +
                    2u * (uint32_t)((buf*128 + wm*64 + mt*16 + lmA_row) * HP + kk + lmA_kof);
                ldsm_x4(a[mt][0], a[mt][1], a[mt][2], a[mt][3], addr);
            }
#pragma unroll
            for (int ntp = 0; ntp < 2; ntp++) {
                uint32_t b00, b01, b10, b11;
                const uint32_t addr = Bs_u +
                    2u * (uint32_t)((buf*128 + wn*32 + ntp*16 + lmB_row) * HP + kk + lmB_kof);
                ldsm_x4(b00, b01, b10, b11, addr);
#pragma unroll
                for (int mt = 0; mt < 4; mt++) {
                    mma_f16(c[mt][2*ntp][0], c[mt][2*ntp][1], c[mt][2*ntp][2], c[mt][2*ntp][3],
                            a[mt][0], a[mt][1], a[mt][2], a[mt][3], b00, b01);
                    mma_f16(c[mt][2*ntp+1][0], c[mt][2*ntp+1][1], c[mt][2*ntp+1][2], c[mt][2*ntp+1][3],
                            a[mt][0], a[mt][1], a[mt][2], a[mt][3], b10, b11);
                }
            }
        }
        if (has_next) {
            const int nb = buf ^ 1;
#pragma unroll
            for (int i = 0; i < 4; i++) {
                __half* da = As + nb*128*HP + (lrow + i*32) * HP + lc4;
                *(uint32_t*)da       = pack_h2(pa[i].x, pa[i].y);
                *(uint32_t*)(da + 2) = pack_h2(pa[i].z, pa[i].w);
                __half* db = Bs + nb*128*HP + (lrow + i*32) * HP + lc4;
                *(uint32_t*)db       = pack_h2(pb[i].x, pb[i].y);
                *(uint32_t*)(db + 2) = pack_h2(pb[i].z, pb[i].w);
            }
            __syncthreads();
        }
    }

    if (blockIdx.z == 0) {
#pragma unroll
        for (int nt = 0; nt < 4; nt++) {
            const int col = n0 + wn*32 + nt*8 + 2*tig;
            const float2 bb = *(const float2*)(bias + col);
#pragma unroll
            for (int mt = 0; mt < 4; mt++) {
                const int row = m0 + wm*64 + mt*16 + gid;
                *(float2*)(g_q + (size_t)row * D_MODEL + col) =
                    make_float2(c[mt][nt][0] + bb.x, c[mt][nt][1] + bb.y);
                *(float2*)(g_q + (size_t)(row + 8) * D_MODEL + col) =
                    make_float2(c[mt][nt][2] + bb.x, c[mt][nt][3] + bb.y);
            }
        }
    } else if (blockIdx.z == 1) {
#pragma unroll
        for (int nt = 0; nt < 4; nt++) {
            const int col = n0 + wn*32 + nt*8 + 2*tig;
            const float2 bb = *(const float2*)(bias + col);
#pragma unroll
            for (int mt = 0; mt < 4; mt++) {
                const int row = m0 + wm*64 + mt*16 + gid;
                *(__half2*)(g_k + (size_t)row * D_MODEL + col) =
                    __floats2half2_rn(c[mt][nt][0] + bb.x, c[mt][nt][1] + bb.y);
                *(__half2*)(g_k + (size_t)(row + 8) * D_MODEL + col) =
                    __floats2half2_rn(c[mt][nt][2] + bb.x, c[mt][nt][3] + bb.y);
            }
        }
    } else {
#pragma unroll
        for (int nt = 0; nt < 4; nt++) {
            const int col = n0 + wn*32 + nt*8 + 2*tig;
            const float2 bb = *(const float2*)(bias + col);
            const int hh = col >> 6;
            const int d0 = col & 63;
#pragma unroll
            for (int mt = 0; mt < 4; mt++) {
                const int row = m0 + wm*64 + mt*16 + gid;
                const int bidx = row >> 11;
                const int sidx = row & 2047;
                __half* base = g_vT + ((size_t)(bidx*NUM_HEADS + hh) * D_HEAD + d0) * SEQ;
                base[sidx]            = __float2half(c[mt][nt][0] + bb.x);
                base[SEQ + sidx]      = __float2half(c[mt][nt][1] + bb.y);
                base[sidx + 8]        = __float2half(c[mt][nt][2] + bb.x);
                base[SEQ + sidx + 8]  = __float2half(c[mt][nt][3] + bb.y);
            }
        }
    }
}

// ============================================================
// Kernel 2 (fp16 tensor core): QEr[bh][s][j] stored at [s][j + delta(s)],
// delta(s) = 1-(s&1), row stride QER_RS.
// ============================================================
__global__ __launch_bounds__(256, 2)
void qer_tc_kernel(const float* __restrict__ Er)
{
    const int bh = blockIdx.z;
    const int b = bh >> 4, h = bh & 15;
    const int j0 = blockIdx.x * 128;
    const int s0 = blockIdx.y * 128;
    if (s0 + j0 + 254 < SEQ - 1) return;

    extern __shared__ __half smh[];
    __half* As = smh;
    __half* Bs = smh + 2*128*HP;
    const uint32_t As_u = (uint32_t)__cvta_generic_to_shared(As);
    const uint32_t Bs_u = (uint32_t)__cvta_generic_to_shared(Bs);

    const int tid = threadIdx.x;
    const int wid = tid >> 5;
    const int lane = tid & 31;
    const int gid = lane >> 2;
    const int tig = lane & 3;
    const int wm = wid >> 2;
    const int wn = wid & 3;

    const int lmA_row = (lane & 7) + ((lane >> 3) & 1) * 8;
    const int lmA_kof = ((lane >> 4) & 1) * 8;
    const int lmB_row = (lane & 7) + ((lane >> 4) & 1) * 8;
    const int lmB_kof = ((lane >> 3) & 1) * 8;

    const float* Ag = g_q + ((size_t)b * SEQ + s0) * D_MODEL + (size_t)h * D_HEAD;
    const float* Bg = Er + (size_t)j0 * D_HEAD;

    float c[4][4][4];
#pragma unroll
    for (int mt = 0; mt < 4; mt++)
#pragma unroll
        for (int nt = 0; nt < 4; nt++)
#pragma unroll
            for (int r = 0; r < 4; r++) c[mt][nt][r] = 0.f;

    const int lrow = tid >> 3;
    const int lc4  = (tid & 7) * 4;

    float4 pa[4], pb[4];
#pragma unroll
    for (int i = 0; i < 4; i++) {
        pa[i] = *(const float4*)(Ag + (size_t)(lrow + i*32) * D_MODEL + lc4);
        pb[i] = *(const float4*)(Bg + (size_t)(lrow + i*32) * D_HEAD + lc4);
    }
#pragma unroll
    for (int i = 0; i < 4; i++) {
        __half* da = As + (lrow + i*32) * HP + lc4;
        *(uint32_t*)da       = pack_h2(pa[i].x, pa[i].y);
        *(uint32_t*)(da + 2) = pack_h2(pa[i].z, pa[i].w);
        __half* db = Bs + (lrow + i*32) * HP + lc4;
        *(uint32_t*)db       = pack_h2(pb[i].x, pb[i].y);
        *(uint32_t*)(db + 2) = pack_h2(pb[i].z, pb[i].w);
    }
    __syncthreads();

    for (int k0 = 0; k0 < D_HEAD; k0 += 32) {
        const int buf = (k0 >> 5) & 1;
        const bool has_next = (k0 + 32) < D_HEAD;
        if (has_next) {
#pragma unroll
            for (int i = 0; i < 4; i++) {
                pa[i] = *(const float4*)(Ag + (size_t)(lrow + i*32) * D_MODEL + k0 + 32 + lc4);
                pb[i] = *(const float4*)(Bg + (size_t)(lrow + i*32) * D_HEAD + k0 + 32 + lc4);
            }
        }
#pragma unroll
        for (int ks = 0; ks < 2; ks++) {
            const int kk = ks * 16;
            uint32_t a[4][4];
#pragma unroll
            for (int mt = 0; mt < 4; mt++) {
                const uint32_t addr = As_u +
                    2u * (uint32_t)((buf*128 + wm*64 + mt*16 + lmA_row) * HP + kk + lmA_kof);
                ldsm_x4(a[mt][0], a[mt][1], a[mt][2], a[mt][3], addr);
            }
#pragma unroll
            for (int ntp = 0; ntp < 2; ntp++) {
                uint32_t b00, b01, b10, b11;
                const uint32_t addr = Bs_u +
                    2u * (uint32_t)((buf*128 + wn*32 + ntp*16 + lmB_row) * HP + kk + lmB_kof);
                ldsm_x4(b00, b01, b10, b11, addr);
#pragma unroll
                for (int mt = 0; mt < 4; mt++) {
                    mma_f16(c[mt][2*ntp][0], c[mt][2*ntp][1], c[mt][2*ntp][2], c[mt][2*ntp][3],
                            a[mt][0], a[mt][1], a[mt][2], a[mt][3], b00, b01);
                    mma_f16(c[mt][2*ntp+1][0], c[mt][2*ntp+1][1], c[mt][2*ntp+1][2], c[mt][2*ntp+1][3],
                            a[mt][0], a[mt][1], a[mt][2], a[mt][3], b10, b11);
                }
            }
        }
        if (has_next) {
            const int nb = buf ^ 1;
#pragma unroll
            for (int i = 0; i < 4; i++) {
                __half* da = As + nb*128*HP + (lrow + i*32) * HP + lc4;
                *(uint32_t*)da       = pack_h2(pa[i].x, pa[i].y);
                *(uint32_t*)(da + 2) = pack_h2(pa[i].z, pa[i].w);
                __half* db = Bs + nb*128*HP + (lrow + i*32) * HP + lc4;
                *(uint32_t*)db       = pack_h2(pb[i].x, pb[i].y);
                *(uint32_t*)(db + 2) = pack_h2(pb[i].z, pb[i].w);
            }
            __syncthreads();
        }
    }

    // store shifted: row s gets column offset delta = 1-(s&1).
    // row parity == gid parity (s0, wm*64, mt*16 all even), uniform per thread.
    __half* dst = g_qer + (size_t)bh * SEQ * QER_RS;
    const int delta = 1 - (gid & 1);
    if (delta == 0) {
#pragma unroll
        for (int nt = 0; nt < 4; nt++) {
            const int col = j0 + wn*32 + nt*8 + 2*tig;
#pragma unroll
            for (int mt = 0; mt < 4; mt++) {
                const int row = s0 + wm*64 + mt*16 + gid;
                *(__half2*)(dst + (size_t)row * QER_RS + col) =
                    __floats2half2_rn(c[mt][nt][0], c[mt][nt][1]);
                *(__half2*)(dst + (size_t)(row + 8) * QER_RS + col) =
                    __floats2half2_rn(c[mt][nt][2], c[mt][nt][3]);
            }
        }
    } else {
#pragma unroll
        for (int nt = 0; nt < 4; nt++) {
            const int col = j0 + wn*32 + nt*8 + 2*tig + 1;
#pragma unroll
            for (int mt = 0; mt < 4; mt++) {
                const int row = s0 + wm*64 + mt*16 + gid;
                dst[(size_t)row * QER_RS + col]         = __float2half(c[mt][nt][0]);
                dst[(size_t)row * QER_RS + col + 1]     = __float2half(c[mt][nt][1]);
                dst[(size_t)(row + 8) * QER_RS + col]     = __float2half(c[mt][nt][2]);
                dst[(size_t)(row + 8) * QER_RS + col + 1] = __float2half(c[mt][nt][3]);
            }
        }
    }
}

// ============================================================
// Kernel 3: fp16 flash attention. P in registers; u32-aligned seed
// loads (parity shift); mask-free main loop for kt < 2*qt.
// ============================================================
#define AHP 72
#define ATT_SMEM_HALVES (2*64*AHP + 2*64*AHP)
#define ATT_SMEM_BYTES (ATT_SMEM_HALVES * 2)   // 36864 B

__global__ __launch_bounds__(256, 2)
void attn_tc_kernel(float* __restrict__ out)
{
    const int qt = gridDim.x - 1 - blockIdx.x;
    const int bh = blockIdx.y;
    const int b = bh >> 4, h = bh & 15;
    const int s0 = qt * 128;

    extern __shared__ __half smh[];
    __half* ks = smh;                    // [2][64][AHP]
    __half* vT = ks + 2*64*AHP;          // [2][64][AHP]

    const int tid = threadIdx.x;
    const int wid = tid >> 5;
    const int lane = tid & 31;
    const int gid = lane >> 2;
    const int tig = lane & 3;
    const int r0 = wid*16 + gid;
    const int r1 = r0 + 8;
    const int sg0 = s0 + r0;
    const int sg1 = s0 + r1;

    const int lmB_row = (lane & 7) + ((lane >> 4) & 1) * 8;
    const int lmB_kof = ((lane >> 3) & 1) * 8;

    const float*  qb  = g_q + ((size_t)b * SEQ + s0) * D_MODEL + (size_t)h * D_HEAD;
    const __half* kb  = g_k + (size_t)b * SEQ * D_MODEL + (size_t)h * D_HEAD;
    const __half* vtb = g_vT + (size_t)bh * D_HEAD * SEQ;
    const __half* qr0 = g_qer + (size_t)bh * SEQ * QER_RS + (size_t)sg0 * QER_RS;
    const __half* qr1 = g_qer + (size_t)bh * SEQ * QER_RS + (size_t)sg1 * QER_RS;
    // rows sg0, sg1 share parity; shifted storage makes these bases even
    const int delta = 1 - (sg0 & 1);
    const int sb0 = 2047 + 2*tig - sg0 + delta;   // even
    const int sb1 = sb0 - 8;                      // even

    // Q fragments resident in registers
    uint32_t qf[4][4];
#pragma unroll
    for (int k4 = 0; k4 < 4; k4++) {
        const int cc = k4*16 + 2*tig;
        const float2 x0 = *(const float2*)(qb + (size_t)r0 * D_MODEL + cc);
        const float2 x1 = *(const float2*)(qb + (size_t)r1 * D_MODEL + cc);
        const float2 x2 = *(const float2*)(qb + (size_t)r0 * D_MODEL + cc + 8);
        const float2 x3 = *(const float2*)(qb + (size_t)r1 * D_MODEL + cc + 8);
        qf[k4][0] = pack_h2(x0.x, x0.y);
        qf[k4][1] = pack_h2(x1.x, x1.y);
        qf[k4][2] = pack_h2(x2.x, x2.y);
        qf[k4][3] = pack_h2(x3.x, x3.y);
    }

    const uint32_t ks_base = (uint32_t)__cvta_generic_to_shared(ks);
    const uint32_t vt_base = (uint32_t)__cvta_generic_to_shared(vT);
    const int ci0 = tid * 2;
    const int ci1 = tid * 2 + 1;
    const int krow0 = ci0 >> 3, ko0 = (ci0 & 7) * 8;
    const int krow1 = ci1 >> 3, ko1 = (ci1 & 7) * 8;

    float o[8][4];
#pragma unroll
    for (int nt = 0; nt < 8; nt++) { o[nt][0]=0.f; o[nt][1]=0.f; o[nt][2]=0.f; o[nt][3]=0.f; }
    float m0v = -1e30f, m1v = -1e30f, l0v = 0.f, l1v = 0.f;
    const int nkt = 2 * qt + 2;

    // prologue: async-load tile 0 into buffer 0
    {
        cp_async16(ks_base + (krow0*AHP + ko0)*2, kb + (size_t)krow0 * D_MODEL + ko0);
        cp_async16(ks_base + (krow1*AHP + ko1)*2, kb + (size_t)krow1 * D_MODEL + ko1);
        cp_async16(vt_base + (krow0*AHP + ko0)*2, vtb + (size_t)krow0 * SEQ + ko0);
        cp_async16(vt_base + (krow1*AHP + ko1)*2, vtb + (size_t)krow1 * SEQ + ko1);
        CP_COMMIT();
    }

    // seed tile 0 rel bias (aligned u32 loads, clamped)
    float s_[8][4];
    {
#pragma unroll
        for (int nt = 0; nt < 8; nt++) {
            int ja = sb0 + nt*8;  ja = ja > 2048 ? 2048 : ja;
            int jc = sb1 + nt*8;  jc = jc > 2048 ? 2048 : jc;
            const uint32_t u0 = *(const uint32_t*)(qr0 + ja);
            const uint32_t u1 = *(const uint32_t*)(qr1 + jc);
            const float2 f0 = __half22float2(*(const __half2*)&u0);
            const float2 f1 = __half22float2(*(const __half2*)&u1);
            s_[nt][0] = f0.x; s_[nt][1] = f0.y;
            s_[nt][2] = f1.x; s_[nt][3] = f1.y;
        }
    }

    for (int kt = 0; kt < nkt; kt++) {
        const int t0 = kt * 64;
        const int buf = kt & 1;
        const bool masked = (kt >= 2*qt);   // uniform per block

        CP_WAIT0();
        __syncthreads();

        if (kt + 1 < nkt) {
            const int t0n = t0 + 64;
            const int boff = (buf ^ 1) * 64 * AHP * 2;
            cp_async16(ks_base + boff + (krow0*AHP + ko0)*2, kb + (size_t)(t0n + krow0) * D_MODEL + ko0);
            cp_async16(ks_base + boff + (krow1*AHP + ko1)*2, kb + (size_t)(t0n + krow1) * D_MODEL + ko1);
            cp_async16(vt_base + boff + (krow0*AHP + ko0)*2, vtb + (size_t)krow0 * SEQ + t0n + ko0);
            cp_async16(vt_base + boff + (krow1*AHP + ko1)*2, vtb + (size_t)krow1 * SEQ + t0n + ko1);
        }
        CP_COMMIT();

        const uint32_t ksb_u = ks_base + (uint32_t)(buf * 64 * AHP * 2);
        const uint32_t vtf_u = vt_base + (uint32_t)(buf * 64 * AHP * 2);

        // S += Q K^T
#pragma unroll
        for (int k4 = 0; k4 < 4; k4++) {
            const int kk = k4 * 16;
#pragma unroll
            for (int ntp = 0; ntp < 4; ntp++) {
                uint32_t b00, b01, b10, b11;
                const uint32_t addr = ksb_u +
                    2u * (uint32_t)((ntp*16 + lmB_row) * AHP + kk + lmB_kof);
                ldsm_x4(b00, b01, b10, b11, addr);
                mma_f16(s_[2*ntp][0], s_[2*ntp][1], s_[2*ntp][2], s_[2*ntp][3],
                        qf[k4][0], qf[k4][1], qf[k4][2], qf[k4][3], b00, b01);
                mma_f16(s_[2*ntp+1][0], s_[2*ntp+1][1], s_[2*ntp+1][2], s_[2*ntp+1][3],
                        qf[k4][0], qf[k4][1], qf[k4][2], qf[k4][3], b10, b11);
            }
        }

        // ---- online softmax, row half 0 ----
        {
            float rmax = -1e30f;
            if (masked) {
#pragma unroll
                for (int nt = 0; nt < 8; nt++) {
                    int tc = t0 + nt*8 + 2*tig;
                    float v0 = s_[nt][0] * 0.125f;
                    float v1 = s_[nt][1] * 0.125f;
                    v0 = (tc     <= sg0) ? v0 : -1e30f;
                    v1 = (tc + 1 <= sg0) ? v1 : -1e30f;
                    s_[nt][0] = v0; s_[nt][1] = v1;
                    rmax = fmaxf(rmax, fmaxf(v0, v1));
                }
            } else {
#pragma unroll
                for (int nt = 0; nt < 8; nt++) {
                    float v0 = s_[nt][0] * 0.125f;
                    float v1 = s_[nt][1] * 0.125f;
                    s_[nt][0] = v0; s_[nt][1] = v1;
                    rmax = fmaxf(rmax, fmaxf(v0, v1));
                }
            }
            rmax = fmaxf(rmax, __shfl_xor_sync(0xffffffffu, rmax, 1));
            rmax = fmaxf(rmax, __shfl_xor_sync(0xffffffffu, rmax, 2));
            float mn = fmaxf(m0v, rmax);
            float alpha = __expf(m0v - mn);
            m0v = mn;
            float lsum = 0.f;
#pragma unroll
            for (int nt = 0; nt < 8; nt++) {
                float p0 = __expf(s_[nt][0] - mn);
                float p1 = __expf(s_[nt][1] - mn);
                lsum += p0 + p1;
                s_[nt][0] = __uint_as_float(pack_h2(p0, p1));
                o[nt][0] *= alpha; o[nt][1] *= alpha;
            }
            lsum += __shfl_xor_sync(0xffffffffu, lsum, 1);
            lsum += __shfl_xor_sync(0xffffffffu, lsum, 2);
            l0v = l0v * alpha + lsum;
        }
        // ---- row half 1 ----
        {
            float rmax = -1e30f;
            if (masked) {
#pragma unroll
                for (int nt = 0; nt < 8; nt++) {
                    int tc = t0 + nt*8 + 2*tig;
                    float v0 = s_[nt][2] * 0.125f;
                    float v1 = s_[nt][3] * 0.125f;
                    v0 = (tc     <= sg1) ? v0 : -1e30f;
                    v1 = (tc + 1 <= sg1) ? v1 : -1e30f;
                    s_[nt][2] = v0; s_[nt][3] = v1;
                    rmax = fmaxf(rmax, fmaxf(v0, v1));
                }
            } else {
#pragma unroll
                for (int nt = 0; nt < 8; nt++) {
                    float v0 = s_[nt][2] * 0.125f;
                    float v1 = s_[nt][3] * 0.125f;
                    s_[nt][2] = v0; s_[nt][3] = v1;
                    rmax = fmaxf(rmax, fmaxf(v0, v1));
                }
            }
            rmax = fmaxf(rmax, __shfl_xor_sync(0xffffffffu, rmax, 1));
            rmax = fmaxf(rmax, __shfl_xor_sync(0xffffffffu, rmax, 2));
            float mn = fmaxf(m1v, rmax);
            float alpha = __expf(m1v - mn);
            m1v = mn;
            float lsum = 0.f;
#pragma unroll
            for (int nt = 0; nt < 8; nt++) {
                float p0 = __expf(s_[nt][2] - mn);
                float p1 = __expf(s_[nt][3] - mn);
                lsum += p0 + p1;
                s_[nt][2] = __uint_as_float(pack_h2(p0, p1));
                o[nt][2] *= alpha; o[nt][3] *= alpha;
            }
            lsum += __shfl_xor_sync(0xffffffffu, lsum, 1);
            lsum += __shfl_xor_sync(0xffffffffu, lsum, 2);
            l1v = l1v * alpha + lsum;
        }

        // O += P V  -- A fragments come directly from packed s_ (C->A reuse)
#pragma unroll
        for (int k4 = 0; k4 < 4; k4++) {
            const int kk = k4 * 16;
            const uint32_t a0 = __float_as_uint(s_[2*k4][0]);
            const uint32_t a1 = __float_as_uint(s_[2*k4][2]);
            const uint32_t a2 = __float_as_uint(s_[2*k4+1][0]);
            const uint32_t a3 = __float_as_uint(s_[2*k4+1][2]);
#pragma unroll
            for (int ntp = 0; ntp < 4; ntp++) {
                uint32_t b00, b01, b10, b11;
                const uint32_t addr = vtf_u +
                    2u * (uint32_t)((ntp*16 + lmB_row) * AHP + kk + lmB_kof);
                ldsm_x4(b00, b01, b10, b11, addr);
                mma_f16(o[2*ntp][0], o[2*ntp][1], o[2*ntp][2], o[2*ntp][3],
                        a0, a1, a2, a3, b00, b01);
                mma_f16(o[2*ntp+1][0], o[2*ntp+1][1], o[2*ntp+1][2], o[2*ntp+1][3],
                        a0, a1, a2, a3, b10, b11);
            }
        }

        // prefetch next tile's rel-bias seeds into s_ (aligned u32, clamped)
        {
            const int t0n = t0 + 64;
#pragma unroll
            for (int nt = 0; nt < 8; nt++) {
                int ja = sb0 + t0n + nt*8;  ja = ja > 2048 ? 2048 : ja;
                int jc = sb1 + t0n + nt*8;  jc = jc > 2048 ? 2048 : jc;
                const uint32_t u0 = *(const uint32_t*)(qr0 + ja);
                const uint32_t u1 = *(const uint32_t*)(qr1 + jc);
                const float2 f0 = __half22float2(*(const __half2*)&u0);
                const float2 f1 = __half22float2(*(const __half2*)&u1);
                s_[nt][0] = f0.x; s_[nt][1] = f0.y;
                s_[nt][2] = f1.x; s_[nt][3] = f1.y;
            }
        }
    }

    // epilogue
    const float inv0 = 1.f / l0v;
    const float inv1 = 1.f / l1v;
    float* ob = out + (size_t)b * SEQ * D_MODEL + (size_t)h * D_HEAD;
#pragma unroll
    for (int nt = 0; nt < 8; nt++) {
        const int d = nt*8 + 2*tig;
        *(float2*)(ob + (size_t)sg0 * D_MODEL + d) = make_float2(o[nt][0]*inv0, o[nt][1]*inv0);
        *(float2*)(ob + (size_t)sg1 * D_MODEL + d) = make_float2(o[nt][2]*inv1, o[nt][3]*inv1);
    }
}

// ============================================================
// launcher
// ============================================================
extern "C" void kernel_launch(void* const* d_in, const int* in_sizes, int n_in,
                              void* d_out, int out_size)
{
    const float* x  = (const float*)d_in[0];
    const float* Wq = (const float*)d_in[1];
    const float* bq = (const float*)d_in[2];
    const float* Wk = (const float*)d_in[3];
    const float* bk = (const float*)d_in[4];
    const float* Wv = (const float*)d_in[5];
    const float* bv = (const float*)d_in[6];
    const float* Er = (const float*)d_in[7];
    float* out = (float*)d_out;

    cudaFuncSetAttribute(qkv_tc_kernel, cudaFuncAttributeMaxDynamicSharedMemorySize,
                         GEMM_SMEM_BYTES);
    cudaFuncSetAttribute(qer_tc_kernel, cudaFuncAttributeMaxDynamicSharedMemorySize,
                         GEMM_SMEM_BYTES);
    cudaFuncSetAttribute(attn_tc_kernel, cudaFuncAttributeMaxDynamicSharedMemorySize,
                         ATT_SMEM_BYTES);

    dim3 g1(D_MODEL / 128, (BATCH * SEQ) / 128, 3);
    qkv_tc_kernel<<<g1, 256, GEMM_SMEM_BYTES>>>(x, Wq, bq, Wk, bk, Wv, bv);

    dim3 g2(SEQ / 128, SEQ / 128, BHN);
    qer_tc_kernel<<<g2, 256, GEMM_SMEM_BYTES>>>(Er);

    dim3 g3(SEQ / 128, BHN);
    attn_tc_kernel<<<g3, 256, ATT_SMEM_BYTES>>>(out);
}

// round 13
// speedup vs baseline: 1.1518x; 1.0295x over previous
#include <cuda_runtime.h>
#include <cuda_fp16.h>
#include <math.h>
#include <stdint.h>

#define D_MODEL 1024
#define NUM_HEADS 16
#define D_HEAD 64
#define BATCH 2
#define SEQ 2048
#define BHN (BATCH*NUM_HEADS)
#define QER_RS 2056   // padded row stride (halves); keeps 16B alignment

// -------- scratch (static device memory; no runtime allocation) --------
__device__ float  g_q  [(size_t)BATCH*SEQ*D_MODEL];          // 16 MB fp32
__device__ __half g_k  [(size_t)BATCH*SEQ*D_MODEL];          // 8 MB fp16
__device__ __half g_vT [(size_t)BHN*D_HEAD*SEQ];             // 8 MB fp16, [bh][d][s]
// row s stored shifted by delta(s) = 1-(s&1) so skew reads are u32-aligned
__device__ __half g_qer[(size_t)BHN*SEQ*QER_RS + 128];       // ~269 MB fp16

// ---------------- helpers ----------------
__device__ __forceinline__ void mma_f16(float& c0, float& c1, float& c2, float& c3,
                                        uint32_t a0, uint32_t a1, uint32_t a2, uint32_t a3,
                                        uint32_t b0, uint32_t b1) {
    asm volatile(
        "mma.sync.aligned.m16n8k16.row.col.f32.f16.f16.f32 "
        "{%0,%1,%2,%3}, {%4,%5,%6,%7}, {%8,%9}, {%0,%1,%2,%3};"
        : "+f"(c0), "+f"(c1), "+f"(c2), "+f"(c3)
        : "r"(a0), "r"(a1), "r"(a2), "r"(a3), "r"(b0), "r"(b1));
}
__device__ __forceinline__ void ldsm_x4(uint32_t& r0, uint32_t& r1, uint32_t& r2, uint32_t& r3,
                                        uint32_t saddr) {
    asm volatile("ldmatrix.sync.aligned.m8n8.x4.shared.b16 {%0,%1,%2,%3}, [%4];"
                 : "=r"(r0), "=r"(r1), "=r"(r2), "=r"(r3) : "r"(saddr));
}
__device__ __forceinline__ uint32_t pack_h2(float x, float y) {
    __half2 h = __floats2half2_rn(x, y);
    return *(uint32_t*)&h;
}
// exp2 of a float pair -> packed half2 (one cvt + one MUFU-class instr)
__device__ __forceinline__ uint32_t exp2_h2(float x, float y) {
    uint32_t u, r;
    asm("cvt.rn.f16x2.f32 %0, %1, %2;" : "=r"(u) : "f"(y), "f"(x));
    asm("ex2.approx.f16x2 %0, %1;" : "=r"(r) : "r"(u));
    return r;
}
__device__ __forceinline__ void cp_async16(uint32_t saddr, const void* g) {
    asm volatile("cp.async.cg.shared.global [%0], [%1], 16;" :: "r"(saddr), "l"(g));
}
#define CP_COMMIT() asm volatile("cp.async.commit_group;")
#define CP_WAIT0()  asm volatile("cp.async.wait_group 0;")

#define ONES_H2 0x3C003C00u
#define SCL 0.18033688011112042f   // 0.125 * log2(e)

// smem geometry for fp16 tensor-core GEMMs: [2 buf][128 rows][HP] halves
#define HP 40
#define GEMM_SMEM_BYTES (2*128*HP*2*2)   // A + B -> 40960 B

// ============================================================
// Kernel 1 (fp16 tensor core): Q/K/V projection.
// ============================================================
__global__ __launch_bounds__(256, 2)
void qkv_tc_kernel(const float* __restrict__ x,
                   const float* __restrict__ Wq, const float* __restrict__ bq,
                   const float* __restrict__ Wk, const float* __restrict__ bk,
                   const float* __restrict__ Wv, const float* __restrict__ bv)
{
    const float* W; const float* bias;
    if (blockIdx.z == 0)      { W = Wq; bias = bq; }
    else if (blockIdx.z == 1) { W = Wk; bias = bk; }
    else                      { W = Wv; bias = bv; }

    extern __shared__ __half smh[];
    __half* As = smh;                // [2][128][HP]
    __half* Bs = smh + 2*128*HP;     // [2][128][HP]
    const uint32_t As_u = (uint32_t)__cvta_generic_to_shared(As);
    const uint32_t Bs_u = (uint32_t)__cvta_generic_to_shared(Bs);

    const int m0 = blockIdx.y * 128;
    const int n0 = blockIdx.x * 128;
    const int tid = threadIdx.x;
    const int wid = tid >> 5;
    const int lane = tid & 31;
    const int gid = lane >> 2;
    const int tig = lane & 3;
    const int wm = wid >> 2;
    const int wn = wid & 3;

    const int lmA_row = (lane & 7) + ((lane >> 3) & 1) * 8;
    const int lmA_kof = ((lane >> 4) & 1) * 8;
    const int lmB_row = (lane & 7) + ((lane >> 4) & 1) * 8;
    const int lmB_kof = ((lane >> 3) & 1) * 8;

    const float* Ag = x + (size_t)m0 * D_MODEL;
    const float* Bg = W + (size_t)n0 * D_MODEL;

    float c[4][4][4];
#pragma unroll
    for (int mt = 0; mt < 4; mt++)
#pragma unroll
        for (int nt = 0; nt < 4; nt++)
#pragma unroll
            for (int r = 0; r < 4; r++) c[mt][nt][r] = 0.f;

    const int lrow = tid >> 3;
    const int lc4  = (tid & 7) * 4;

    float4 pa[4], pb[4];
#pragma unroll
    for (int i = 0; i < 4; i++) {
        pa[i] = *(const float4*)(Ag + (size_t)(lrow + i*32) * D_MODEL + lc4);
        pb[i] = *(const float4*)(Bg + (size_t)(lrow + i*32) * D_MODEL + lc4);
    }
#pragma unroll
    for (int i = 0; i < 4; i++) {
        __half* da = As + (lrow + i*32) * HP + lc4;
        *(uint32_t*)da       = pack_h2(pa[i].x, pa[i].y);
        *(uint32_t*)(da + 2) = pack_h2(pa[i].z, pa[i].w);
        __half* db = Bs + (lrow + i*32) * HP + lc4;
        *(uint32_t*)db       = pack_h2(pb[i].x, pb[i].y);
        *(uint32_t*)(db + 2) = pack_h2(pb[i].z, pb[i].w);
    }
    __syncthreads();

    for (int k0 = 0; k0 < D_MODEL; k0 += 32) {
        const int buf = (k0 >> 5) & 1;
        const bool has_next = (k0 + 32) < D_MODEL;
        if (has_next) {
#pragma unroll
            for (int i = 0; i < 4; i++) {
                pa[i] = *(const float4*)(Ag + (size_t)(lrow + i*32) * D_MODEL + k0 + 32 + lc4);
                pb[i] = *(const float4*)(Bg + (size_t)(lrow + i*32) * D_MODEL + k0 + 32 + lc4);
            }
        }
#pragma unroll
        for (int ks = 0; ks < 2; ks++) {
            const int kk = ks * 16;
            uint32_t a[4][4];
#pragma unroll
            for (int mt = 0; mt < 4; mt++) {
                const uint32_t addr = As_u +
                    2u * (uint32_t)((buf*128 + wm*64 + mt*16 + lmA_row) * HP + kk + lmA_kof);
                ldsm_x4(a[mt][0], a[mt][1], a[mt][2], a[mt][3], addr);
            }
#pragma unroll
            for (int ntp = 0; ntp < 2; ntp++) {
                uint32_t b00, b01, b10, b11;
                const uint32_t addr = Bs_u +
                    2u * (uint32_t)((buf*128 + wn*32 + ntp*16 + lmB_row) * HP + kk + lmB_kof);
                ldsm_x4(b00, b01, b10, b11, addr);
#pragma unroll
                for (int mt = 0; mt < 4; mt++) {
                    mma_f16(c[mt][2*ntp][0], c[mt][2*ntp][1], c[mt][2*ntp][2], c[mt][2*ntp][3],
                            a[mt][0], a[mt][1], a[mt][2], a[mt][3], b00, b01);
                    mma_f16(c[mt][2*ntp+1][0], c[mt][2*ntp+1][1], c[mt][2*ntp+1][2], c[mt][2*ntp+1][3],
                            a[mt][0], a[mt][1], a[mt][2], a[mt][3], b10, b11);
                }
            }
        }
        if (has_next) {
            const int nb = buf ^ 1;
#pragma unroll
            for (int i = 0; i < 4; i++) {
                __half* da = As + nb*128*HP + (lrow + i*32) * HP + lc4;
                *(uint32_t*)da       = pack_h2(pa[i].x, pa[i].y);
                *(uint32_t*)(da + 2) = pack_h2(pa[i].z, pa[i].w);
                __half* db = Bs + nb*128*HP + (lrow + i*32) * HP + lc4;
                *(uint32_t*)db       = pack_h2(pb[i].x, pb[i].y);
                *(uint32_t*)(db + 2) = pack_h2(pb[i].z, pb[i].w);
            }
            __syncthreads();
        }
    }

    if (blockIdx.z == 0) {
#pragma unroll
        for (int nt = 0; nt < 4; nt++) {
            const int col = n0 + wn*32 + nt*8 + 2*tig;
            const float2 bb = *(const float2*)(bias + col);
#pragma unroll
            for (int mt = 0; mt < 4; mt++) {
                const int row = m0 + wm*64 + mt*16 + gid;
                *(float2*)(g_q + (size_t)row * D_MODEL + col) =
                    make_float2(c[mt][nt][0] + bb.x, c[mt][nt][1] + bb.y);
                *(float2*)(g_q + (size_t)(row + 8) * D_MODEL + col) =
                    make_float2(c[mt][nt][2] + bb.x, c[mt][nt][3] + bb.y);
            }
        }
    } else if (blockIdx.z == 1) {
#pragma unroll
        for (int nt = 0; nt < 4; nt++) {
            const int col = n0 + wn*32 + nt*8 + 2*tig;
            const float2 bb = *(const float2*)(bias + col);
#pragma unroll
            for (int mt = 0; mt < 4; mt++) {
                const int row = m0 + wm*64 + mt*16 + gid;
                *(__half2*)(g_k + (size_t)row * D_MODEL + col) =
                    __floats2half2_rn(c[mt][nt][0] + bb.x, c[mt][nt][1] + bb.y);
                *(__half2*)(g_k + (size_t)(row + 8) * D_MODEL + col) =
                    __floats2half2_rn(c[mt][nt][2] + bb.x, c[mt][nt][3] + bb.y);
            }
        }
    } else {
#pragma unroll
        for (int nt = 0; nt < 4; nt++) {
            const int col = n0 + wn*32 + nt*8 + 2*tig;
            const float2 bb = *(const float2*)(bias + col);
            const int hh = col >> 6;
            const int d0 = col & 63;
#pragma unroll
            for (int mt = 0; mt < 4; mt++) {
                const int row = m0 + wm*64 + mt*16 + gid;
                const int bidx = row >> 11;
                const int sidx = row & 2047;
                __half* base = g_vT + ((size_t)(bidx*NUM_HEADS + hh) * D_HEAD + d0) * SEQ;
                base[sidx]            = __float2half(c[mt][nt][0] + bb.x);
                base[SEQ + sidx]      = __float2half(c[mt][nt][1] + bb.y);
                base[sidx + 8]        = __float2half(c[mt][nt][2] + bb.x);
                base[SEQ + sidx + 8]  = __float2half(c[mt][nt][3] + bb.y);
            }
        }
    }
}

// ============================================================
// Kernel 2 (fp16 tensor core): QEr[bh][s][j] stored at [s][j + delta(s)],
// delta(s) = 1-(s&1), row stride QER_RS.
// ============================================================
__global__ __launch_bounds__(256, 2)
void qer_tc_kernel(const float* __restrict__ Er)
{
    const int bh = blockIdx.z;
    const int b = bh >> 4, h = bh & 15;
    const int j0 = blockIdx.x * 128;
    const int s0 = blockIdx.y * 128;
    if (s0 + j0 + 254 < SEQ - 1) return;

    extern __shared__ __half smh[];
    __half* As = smh;
    __half* Bs = smh + 2*128*HP;
    const uint32_t As_u = (uint32_t)__cvta_generic_to_shared(As);
    const uint32_t Bs_u = (uint32_t)__cvta_generic_to_shared(Bs);

    const int tid = threadIdx.x;
    const int wid = tid >> 5;
    const int lane = tid & 31;
    const int gid = lane >> 2;
    const int tig = lane & 3;
    const int wm = wid >> 2;
    const int wn = wid & 3;

    const int lmA_row = (lane & 7) + ((lane >> 3) & 1) * 8;
    const int lmA_kof = ((lane >> 4) & 1) * 8;
    const int lmB_row = (lane & 7) + ((lane >> 4) & 1) * 8;
    const int lmB_kof = ((lane >> 3) & 1) * 8;

    const float* Ag = g_q + ((size_t)b * SEQ + s0) * D_MODEL + (size_t)h * D_HEAD;
    const float* Bg = Er + (size_t)j0 * D_HEAD;

    float c[4][4][4];
#pragma unroll
    for (int mt = 0; mt < 4; mt++)
#pragma unroll
        for (int nt = 0; nt < 4; nt++)
#pragma unroll
            for (int r = 0; r < 4; r++) c[mt][nt][r] = 0.f;

    const int lrow = tid >> 3;
    const int lc4  = (tid & 7) * 4;

    float4 pa[4], pb[4];
#pragma unroll
    for (int i = 0; i < 4; i++) {
        pa[i] = *(const float4*)(Ag + (size_t)(lrow + i*32) * D_MODEL + lc4);
        pb[i] = *(const float4*)(Bg + (size_t)(lrow + i*32) * D_HEAD + lc4);
    }
#pragma unroll
    for (int i = 0; i < 4; i++) {
        __half* da = As + (lrow + i*32) * HP + lc4;
        *(uint32_t*)da       = pack_h2(pa[i].x, pa[i].y);
        *(uint32_t*)(da + 2) = pack_h2(pa[i].z, pa[i].w);
        __half* db = Bs + (lrow + i*32) * HP + lc4;
        *(uint32_t*)db       = pack_h2(pb[i].x, pb[i].y);
        *(uint32_t*)(db + 2) = pack_h2(pb[i].z, pb[i].w);
    }
    __syncthreads();

    for (int k0 = 0; k0 < D_HEAD; k0 += 32) {
        const int buf = (k0 >> 5) & 1;
        const bool has_next = (k0 + 32) < D_HEAD;
        if (has_next) {
#pragma unroll
            for (int i = 0; i < 4; i++) {
                pa[i] = *(const float4*)(Ag + (size_t)(lrow + i*32) * D_MODEL + k0 + 32 + lc4);
                pb[i] = *(const float4*)(Bg + (size_t)(lrow + i*32) * D_HEAD + k0 + 32 + lc4);
            }
        }
#pragma unroll
        for (int ks = 0; ks < 2; ks++) {
            const int kk = ks * 16;
            uint32_t a[4][4];
#pragma unroll
            for (int mt = 0; mt < 4; mt++) {
                const uint32_t addr = As_u +
                    2u * (uint32_t)((buf*128 + wm*64 + mt*16 + lmA_row) * HP + kk + lmA_kof);
                ldsm_x4(a[mt][0], a[mt][1], a[mt][2], a[mt][3], addr);
            }
#pragma unroll
            for (int ntp = 0; ntp < 2; ntp++) {
                uint32_t b00, b01, b10, b11;
                const uint32_t addr = Bs_u +
                    2u * (uint32_t)((buf*128 + wn*32 + ntp*16 + lmB_row) * HP + kk + lmB_kof);
                ldsm_x4(b00, b01, b10, b11, addr);
#pragma unroll
                for (int mt = 0; mt < 4; mt++) {
                    mma_f16(c[mt][2*ntp][0], c[mt][2*ntp][1], c[mt][2*ntp][2], c[mt][2*ntp][3],
                            a[mt][0], a[mt][1], a[mt][2], a[mt][3], b00, b01);
                    mma_f16(c[mt][2*ntp+1][0], c[mt][2*ntp+1][1], c[mt][2*ntp+1][2], c[mt][2*ntp+1][3],
                            a[mt][0], a[mt][1], a[mt][2], a[mt][3], b10, b11);
                }
            }
        }
        if (has_next) {
            const int nb = buf ^ 1;
#pragma unroll
            for (int i = 0; i < 4; i++) {
                __half* da = As + nb*128*HP + (lrow + i*32) * HP + lc4;
                *(uint32_t*)da       = pack_h2(pa[i].x, pa[i].y);
                *(uint32_t*)(da + 2) = pack_h2(pa[i].z, pa[i].w);
                __half* db = Bs + nb*128*HP + (lrow + i*32) * HP + lc4;
                *(uint32_t*)db       = pack_h2(pb[i].x, pb[i].y);
                *(uint32_t*)(db + 2) = pack_h2(pb[i].z, pb[i].w);
            }
            __syncthreads();
        }
    }

    // store shifted: row s gets column offset delta = 1-(s&1).
    __half* dst = g_qer + (size_t)bh * SEQ * QER_RS;
    const int delta = 1 - (gid & 1);
    if (delta == 0) {
#pragma unroll
        for (int nt = 0; nt < 4; nt++) {
            const int col = j0 + wn*32 + nt*8 + 2*tig;
#pragma unroll
            for (int mt = 0; mt < 4; mt++) {
                const int row = s0 + wm*64 + mt*16 + gid;
                *(__half2*)(dst + (size_t)row * QER_RS + col) =
                    __floats2half2_rn(c[mt][nt][0], c[mt][nt][1]);
                *(__half2*)(dst + (size_t)(row + 8) * QER_RS + col) =
                    __floats2half2_rn(c[mt][nt][2], c[mt][nt][3]);
            }
        }
    } else {
#pragma unroll
        for (int nt = 0; nt < 4; nt++) {
            const int col = j0 + wn*32 + nt*8 + 2*tig + 1;
#pragma unroll
            for (int mt = 0; mt < 4; mt++) {
                const int row = s0 + wm*64 + mt*16 + gid;
                dst[(size_t)row * QER_RS + col]         = __float2half(c[mt][nt][0]);
                dst[(size_t)row * QER_RS + col + 1]     = __float2half(c[mt][nt][1]);
                dst[(size_t)(row + 8) * QER_RS + col]     = __float2half(c[mt][nt][2]);
                dst[(size_t)(row + 8) * QER_RS + col + 1] = __float2half(c[mt][nt][3]);
            }
        }
    }
}

// ============================================================
// Kernel 3: fp16 flash attention. log2-domain softmax with
// ex2.approx.f16x2; l via all-ones mma column; P in registers.
// ============================================================
#define AHP 72
#define ATT_SMEM_HALVES (2*64*AHP + 2*64*AHP)
#define ATT_SMEM_BYTES (ATT_SMEM_HALVES * 2)   // 36864 B

__global__ __launch_bounds__(256, 2)
void attn_tc_kernel(float* __restrict__ out)
{
    const int qt = gridDim.x - 1 - blockIdx.x;
    const int bh = blockIdx.y;
    const int b = bh >> 4, h = bh & 15;
    const int s0 = qt * 128;

    extern __shared__ __half smh[];
    __half* ks = smh;                    // [2][64][AHP]
    __half* vT = ks + 2*64*AHP;          // [2][64][AHP]

    const int tid = threadIdx.x;
    const int wid = tid >> 5;
    const int lane = tid & 31;
    const int gid = lane >> 2;
    const int tig = lane & 3;
    const int r0 = wid*16 + gid;
    const int r1 = r0 + 8;
    const int sg0 = s0 + r0;
    const int sg1 = s0 + r1;

    const int lmB_row = (lane & 7) + ((lane >> 4) & 1) * 8;
    const int lmB_kof = ((lane >> 3) & 1) * 8;

    const float*  qb  = g_q + ((size_t)b * SEQ + s0) * D_MODEL + (size_t)h * D_HEAD;
    const __half* kb  = g_k + (size_t)b * SEQ * D_MODEL + (size_t)h * D_HEAD;
    const __half* vtb = g_vT + (size_t)bh * D_HEAD * SEQ;
    const __half* qr0 = g_qer + (size_t)bh * SEQ * QER_RS + (size_t)sg0 * QER_RS;
    const __half* qr1 = g_qer + (size_t)bh * SEQ * QER_RS + (size_t)sg1 * QER_RS;
    const int delta = 1 - (sg0 & 1);
    const int sb0 = 2047 + 2*tig - sg0 + delta;   // even
    const int sb1 = sb0 - 8;                      // even

    // Q fragments resident in registers
    uint32_t qf[4][4];
#pragma unroll
    for (int k4 = 0; k4 < 4; k4++) {
        const int cc = k4*16 + 2*tig;
        const float2 x0 = *(const float2*)(qb + (size_t)r0 * D_MODEL + cc);
        const float2 x1 = *(const float2*)(qb + (size_t)r1 * D_MODEL + cc);
        const float2 x2 = *(const float2*)(qb + (size_t)r0 * D_MODEL + cc + 8);
        const float2 x3 = *(const float2*)(qb + (size_t)r1 * D_MODEL + cc + 8);
        qf[k4][0] = pack_h2(x0.x, x0.y);
        qf[k4][1] = pack_h2(x1.x, x1.y);
        qf[k4][2] = pack_h2(x2.x, x2.y);
        qf[k4][3] = pack_h2(x3.x, x3.y);
    }

    const uint32_t ks_base = (uint32_t)__cvta_generic_to_shared(ks);
    const uint32_t vt_base = (uint32_t)__cvta_generic_to_shared(vT);
    const int ci0 = tid * 2;
    const int ci1 = tid * 2 + 1;
    const int krow0 = ci0 >> 3, ko0 = (ci0 & 7) * 8;
    const int krow1 = ci1 >> 3, ko1 = (ci1 & 7) * 8;

    float o[8][4];
#pragma unroll
    for (int nt = 0; nt < 8; nt++) { o[nt][0]=0.f; o[nt][1]=0.f; o[nt][2]=0.f; o[nt][3]=0.f; }
    float lacc[4] = {0.f, 0.f, 0.f, 0.f};
    float m0v = -1e30f, m1v = -1e30f;
    const int nkt = 2 * qt + 2;

    // prologue: async-load tile 0 into buffer 0
    {
        cp_async16(ks_base + (krow0*AHP + ko0)*2, kb + (size_t)krow0 * D_MODEL + ko0);
        cp_async16(ks_base + (krow1*AHP + ko1)*2, kb + (size_t)krow1 * D_MODEL + ko1);
        cp_async16(vt_base + (krow0*AHP + ko0)*2, vtb + (size_t)krow0 * SEQ + ko0);
        cp_async16(vt_base + (krow1*AHP + ko1)*2, vtb + (size_t)krow1 * SEQ + ko1);
        CP_COMMIT();
    }

    // seed tile 0 rel bias (aligned u32 loads, clamped)
    float s_[8][4];
    {
#pragma unroll
        for (int nt = 0; nt < 8; nt++) {
            int ja = sb0 + nt*8;  ja = ja > 2048 ? 2048 : ja;
            int jc = sb1 + nt*8;  jc = jc > 2048 ? 2048 : jc;
            const uint32_t u0 = *(const uint32_t*)(qr0 + ja);
            const uint32_t u1 = *(const uint32_t*)(qr1 + jc);
            const float2 f0 = __half22float2(*(const __half2*)&u0);
            const float2 f1 = __half22float2(*(const __half2*)&u1);
            s_[nt][0] = f0.x; s_[nt][1] = f0.y;
            s_[nt][2] = f1.x; s_[nt][3] = f1.y;
        }
    }

    for (int kt = 0; kt < nkt; kt++) {
        const int t0 = kt * 64;
        const int buf = kt & 1;
        const bool masked = (kt >= 2*qt);   // uniform per block

        CP_WAIT0();
        __syncthreads();

        if (kt + 1 < nkt) {
            const int t0n = t0 + 64;
            const int boff = (buf ^ 1) * 64 * AHP * 2;
            cp_async16(ks_base + boff + (krow0*AHP + ko0)*2, kb + (size_t)(t0n + krow0) * D_MODEL + ko0);
            cp_async16(ks_base + boff + (krow1*AHP + ko1)*2, kb + (size_t)(t0n + krow1) * D_MODEL + ko1);
            cp_async16(vt_base + boff + (krow0*AHP + ko0)*2, vtb + (size_t)krow0 * SEQ + t0n + ko0);
            cp_async16(vt_base + boff + (krow1*AHP + ko1)*2, vtb + (size_t)krow1 * SEQ + t0n + ko1);
        }
        CP_COMMIT();

        const uint32_t ksb_u = ks_base + (uint32_t)(buf * 64 * AHP * 2);
        const uint32_t vtf_u = vt_base + (uint32_t)(buf * 64 * AHP * 2);

        // S += Q K^T
#pragma unroll
        for (int k4 = 0; k4 < 4; k4++) {
            const int kk = k4 * 16;
#pragma unroll
            for (int ntp = 0; ntp < 4; ntp++) {
                uint32_t b00, b01, b10, b11;
                const uint32_t addr = ksb_u +
                    2u * (uint32_t)((ntp*16 + lmB_row) * AHP + kk + lmB_kof);
                ldsm_x4(b00, b01, b10, b11, addr);
                mma_f16(s_[2*ntp][0], s_[2*ntp][1], s_[2*ntp][2], s_[2*ntp][3],
                        qf[k4][0], qf[k4][1], qf[k4][2], qf[k4][3], b00, b01);
                mma_f16(s_[2*ntp+1][0], s_[2*ntp+1][1], s_[2*ntp+1][2], s_[2*ntp+1][3],
                        qf[k4][0], qf[k4][1], qf[k4][2], qf[k4][3], b10, b11);
            }
        }

        // ---- online softmax (log2 domain), row half 0 ----
        {
            float rmax = -1e30f;
            if (masked) {
#pragma unroll
                for (int nt = 0; nt < 8; nt++) {
                    int tc = t0 + nt*8 + 2*tig;
                    float v0 = s_[nt][0] * SCL;
                    float v1 = s_[nt][1] * SCL;
                    v0 = (tc     <= sg0) ? v0 : -1e30f;
                    v1 = (tc + 1 <= sg0) ? v1 : -1e30f;
                    s_[nt][0] = v0; s_[nt][1] = v1;
                    rmax = fmaxf(rmax, fmaxf(v0, v1));
                }
            } else {
#pragma unroll
                for (int nt = 0; nt < 8; nt++) {
                    float v0 = s_[nt][0] * SCL;
                    float v1 = s_[nt][1] * SCL;
                    s_[nt][0] = v0; s_[nt][1] = v1;
                    rmax = fmaxf(rmax, fmaxf(v0, v1));
                }
            }
            rmax = fmaxf(rmax, __shfl_xor_sync(0xffffffffu, rmax, 1));
            rmax = fmaxf(rmax, __shfl_xor_sync(0xffffffffu, rmax, 2));
            float mn = fmaxf(m0v, rmax);
            float alpha = exp2f(m0v - mn);
            m0v = mn;
            lacc[0] *= alpha;
#pragma unroll
            for (int nt = 0; nt < 8; nt++) {
                s_[nt][0] = __uint_as_float(exp2_h2(s_[nt][0] - mn, s_[nt][1] - mn));
                o[nt][0] *= alpha; o[nt][1] *= alpha;
            }
        }
        // ---- row half 1 ----
        {
            float rmax = -1e30f;
            if (masked) {
#pragma unroll
                for (int nt = 0; nt < 8; nt++) {
                    int tc = t0 + nt*8 + 2*tig;
                    float v0 = s_[nt][2] * SCL;
                    float v1 = s_[nt][3] * SCL;
                    v0 = (tc     <= sg1) ? v0 : -1e30f;
                    v1 = (tc + 1 <= sg1) ? v1 : -1e30f;
                    s_[nt][2] = v0; s_[nt][3] = v1;
                    rmax = fmaxf(rmax, fmaxf(v0, v1));
                }
            } else {
#pragma unroll
                for (int nt = 0; nt < 8; nt++) {
                    float v0 = s_[nt][2] * SCL;
                    float v1 = s_[nt][3] * SCL;
                    s_[nt][2] = v0; s_[nt][3] = v1;
                    rmax = fmaxf(rmax, fmaxf(v0, v1));
                }
            }
            rmax = fmaxf(rmax, __shfl_xor_sync(0xffffffffu, rmax, 1));
            rmax = fmaxf(rmax, __shfl_xor_sync(0xffffffffu, rmax, 2));
            float mn = fmaxf(m1v, rmax);
            float alpha = exp2f(m1v - mn);
            m1v = mn;
            lacc[2] *= alpha;
#pragma unroll
            for (int nt = 0; nt < 8; nt++) {
                s_[nt][2] = __uint_as_float(exp2_h2(s_[nt][2] - mn, s_[nt][3] - mn));
                o[nt][2] *= alpha; o[nt][3] *= alpha;
            }
        }

        // O += P V ; l += P 1   (A fragments from packed s_, C->A reuse)
#pragma unroll
        for (int k4 = 0; k4 < 4; k4++) {
            const int kk = k4 * 16;
            const uint32_t a0 = __float_as_uint(s_[2*k4][0]);
            const uint32_t a1 = __float_as_uint(s_[2*k4][2]);
            const uint32_t a2 = __float_as_uint(s_[2*k4+1][0]);
            const uint32_t a3 = __float_as_uint(s_[2*k4+1][2]);
#pragma unroll
            for (int ntp = 0; ntp < 4; ntp++) {
                uint32_t b00, b01, b10, b11;
                const uint32_t addr = vtf_u +
                    2u * (uint32_t)((ntp*16 + lmB_row) * AHP + kk + lmB_kof);
                ldsm_x4(b00, b01, b10, b11, addr);
                mma_f16(o[2*ntp][0], o[2*ntp][1], o[2*ntp][2], o[2*ntp][3],
                        a0, a1, a2, a3, b00, b01);
                mma_f16(o[2*ntp+1][0], o[2*ntp+1][1], o[2*ntp+1][2], o[2*ntp+1][3],
                        a0, a1, a2, a3, b10, b11);
            }
            // row-sum accumulator (all-ones B fragment)
            mma_f16(lacc[0], lacc[1], lacc[2], lacc[3],
                    a0, a1, a2, a3, ONES_H2, ONES_H2);
        }

        // prefetch next tile's rel-bias seeds into s_ (aligned u32, clamped)
        {
            const int t0n = t0 + 64;
#pragma unroll
            for (int nt = 0; nt < 8; nt++) {
                int ja = sb0 + t0n + nt*8;  ja = ja > 2048 ? 2048 : ja;
                int jc = sb1 + t0n + nt*8;  jc = jc > 2048 ? 2048 : jc;
                const uint32_t u0 = *(const uint32_t*)(qr0 + ja);
                const uint32_t u1 = *(const uint32_t*)(qr1 + jc);
                const float2 f0 = __half22float2(*(const __half2*)&u0);
                const float2 f1 = __half22float2(*(const __half2*)&u1);
                s_[nt][0] = f0.x; s_[nt][1] = f0.y;
                s_[nt][2] = f1.x; s_[nt][3] = f1.y;
            }
        }
    }

    // epilogue
    const float inv0 = 1.f / lacc[0];
    const float inv1 = 1.f / lacc[2];
    float* ob = out + (size_t)b * SEQ * D_MODEL + (size_t)h * D_HEAD;
#pragma unroll
    for (int nt = 0; nt < 8; nt++) {
        const int d = nt*8 + 2*tig;
        *(float2*)(ob + (size_t)sg0 * D_MODEL + d) = make_float2(o[nt][0]*inv0, o[nt][1]*inv0);
        *(float2*)(ob + (size_t)sg1 * D_MODEL + d) = make_float2(o[nt][2]*inv1, o[nt][3]*inv1);
    }
}

// ============================================================
// launcher
// ============================================================
extern "C" void kernel_launch(void* const* d_in, const int* in_sizes, int n_in,
                              void* d_out, int out_size)
{
    const float* x  = (const float*)d_in[0];
    const float* Wq = (const float*)d_in[1];
    const float* bq = (const float*)d_in[2];
    const float* Wk = (const float*)d_in[3];
    const float* bk = (const float*)d_in[4];
    const float* Wv = (const float*)d_in[5];
    const float* bv = (const float*)d_in[6];
    const float* Er = (const float*)d_in[7];
    float* out = (float*)d_out;

    cudaFuncSetAttribute(qkv_tc_kernel, cudaFuncAttributeMaxDynamicSharedMemorySize,
                         GEMM_SMEM_BYTES);
    cudaFuncSetAttribute(qer_tc_kernel, cudaFuncAttributeMaxDynamicSharedMemorySize,
                         GEMM_SMEM_BYTES);
    cudaFuncSetAttribute(attn_tc_kernel, cudaFuncAttributeMaxDynamicSharedMemorySize,
                         ATT_SMEM_BYTES);

    dim3 g1(D_MODEL / 128, (BATCH * SEQ) / 128, 3);
    qkv_tc_kernel<<<g1, 256, GEMM_SMEM_BYTES>>>(x, Wq, bq, Wk, bk, Wv, bv);

    dim3 g2(SEQ / 128, SEQ / 128, BHN);
    qer_tc_kernel<<<g2, 256, GEMM_SMEM_BYTES>>>(Er);

    dim3 g3(SEQ / 128, BHN);
    attn_tc_kernel<<<g3, 256, ATT_SMEM_BYTES>>>(out);
}